// round 4
// baseline (speedup 1.0000x reference)
#include <cuda_runtime.h>

// ---------------------------------------------------------------------------
// Quantized LeNet, exact fixed-point semantics.
// APREC=8, PPREC=8, IWIDTH=3 -> clamp to [-8.0, +7.0], grid 1/256.
//
// round_half_even(x * w256) == fmaf(x, w256, MAGIC) - MAGIC (MAGIC=1.5*2^23).
// Fast path (clamp provably a no-op): fma.rn.f32x2 computes TWO pixel
// roundings per fma instruction; IADD3 merges TWO taps per alu instruction;
// the magic bias is removed once via acc init = bias - ntaps*MAGICI (mod 2^32).
// Slow clamped scalar path is kept behind a uniform branch for any input.
// ---------------------------------------------------------------------------

typedef unsigned long long ull;

#define MAGICF 12582912.0f
#define MAGICI 0x4B400000u
#define MAGICIi 0x4B400000
#define MAGIC2 0x4B4000004B400000ULL
#define CLAMP_LO (MAGICF - 2048.0f)
#define CLAMP_HI (MAGICF + 1792.0f)   // QMAX = +7.0
#define QLO (-2048)
#define QHI 1792
#define SAFE_BOUND 458624             // 1792*256 - 128

// Output layout (float offsets) — tuple order of reference():
#define OFF_LOGP   0
#define OFF_C1IN   20480
#define OFF_C1OUT  1626112
#define OFF_C2IN   13422592
#define OFF_C2OUT  16371712
#define OFF_FC1IN  18993152
#define OFF_FC1OUT 19648512
#define OFF_FC2IN  19750912
#define OFF_FC2OUT 19853312

// Prequantized parameters + flags (device scratch — no allocations).
__device__ float g_w1[256];          // conv1 w*256 scalar (slow path)
__device__ ull   g_w1b[256];         // conv1 w*256 broadcast pairs (w,w)
__device__ int   g_b1[16];
__device__ float g_w2p[8000];        // conv2 w*256 scalar, [20][10][5][8]
__device__ ull   g_w2b[6016];        // conv2 broadcast pairs, [20][10][5][6]
__device__ int   g_b2[32];
__device__ int   g_f1w[16000];
__device__ int   g_f1b[64];
__device__ int   g_f2w[512];
__device__ int   g_f2b[16];
__device__ int   g_maxx;
__device__ int   g_maxc1;
__device__ int   g_maxw1;
__device__ int   g_maxw2;

__device__ __forceinline__ int iclamp(int v, int lo, int hi) {
    return v < lo ? lo : (v > hi ? hi : v);
}
__device__ __forceinline__ int rhe8(int S) {
    return (S + 127 + ((S >> 8) & 1)) >> 8;
}
__device__ __forceinline__ unsigned lo32(ull v) { return (unsigned)v; }
__device__ __forceinline__ unsigned hi32(ull v) { return (unsigned)(v >> 32); }
__device__ __forceinline__ ull mkpack(unsigned lo, unsigned hi) {
    ull d;
    asm("mov.b64 %0, {%1, %2};" : "=l"(d) : "r"(lo), "r"(hi));
    return d;
}
// packed fma with magic bias: (round(xlo*wlo)+MAGIC, round(xhi*whi)+MAGIC)
__device__ __forceinline__ ull ffma2m(ull x, ull w) {
    ull d;
    ull m = MAGIC2;
    asm("fma.rn.f32x2 %0, %1, %2, %3;" : "=l"(d) : "l"(x), "l"(w), "l"(m));
    return d;
}

template <int NW>
__device__ __forceinline__ void blockAtomicMax(int v, int* dst) {
    __shared__ int sm[NW];
    v = __reduce_max_sync(0xffffffffu, v);
    int w = threadIdx.x >> 5;
    if ((threadIdx.x & 31) == 0) sm[w] = v;
    __syncthreads();
    if (threadIdx.x == 0) {
        int m = sm[0];
#pragma unroll
        for (int i = 1; i < NW; i++) m = max(m, sm[i]);
        atomicMax(dst, m);
    }
}

__device__ __forceinline__ void loadrow28(float* xr, const float* p) {
#pragma unroll
    for (int i = 0; i < 7; i++) {
        float4 v = ((const float4*)p)[i];
        xr[4 * i + 0] = v.x; xr[4 * i + 1] = v.y;
        xr[4 * i + 2] = v.z; xr[4 * i + 3] = v.w;
    }
}

// ---------------------------------------------------------------------------
__global__ void prep_kernel(const float* __restrict__ w1, const float* __restrict__ b1,
                            const float* __restrict__ w2, const float* __restrict__ b2,
                            const float* __restrict__ f1w, const float* __restrict__ f1b,
                            const float* __restrict__ f2w, const float* __restrict__ f2b) {
    __shared__ int sm1[8], sm2[8];
    int t = threadIdx.x;
    int m1 = 0, m2 = 0;
    for (int i = t; i < 250; i += 256) {
        float q = rintf(w1[i] * 256.0f);
        g_w1[i] = q;
        unsigned u = __float_as_uint(q);
        g_w1b[i] = ((ull)u << 32) | u;
        m1 = max(m1, abs((int)q));
    }
    for (int i = t; i < 10; i += 256) g_b1[i] = __float2int_rn(b1[i] * 256.0f);
    // conv2 scalar padded [20][10][5][8]
    for (int i = t; i < 8000; i += 256) {
        int q = i & 7;
        int rest = i >> 3;
        int p = rest % 5;
        int cc = rest / 5;
        int cin = cc % 10;
        int cout = cc / 10;
        float v = 0.0f;
        if (q < 5) {
            v = rintf(w2[((cout * 10 + cin) * 5 + p) * 5 + q] * 256.0f);
            m2 = max(m2, abs((int)v));
        }
        g_w2p[i] = v;
    }
    // conv2 broadcast pairs [20][10][5][6]
    for (int i = t; i < 6000; i += 256) {
        int q = i % 6;
        int rest = i / 6;
        int p = rest % 5;
        int cc = rest / 5;
        int cin = cc % 10;
        int cout = cc / 10;
        float v = 0.0f;
        if (q < 5) v = rintf(w2[((cout * 10 + cin) * 5 + p) * 5 + q] * 256.0f);
        unsigned u = __float_as_uint(v);
        g_w2b[i] = ((ull)u << 32) | u;
    }
    for (int i = t; i < 20; i += 256) g_b2[i] = __float2int_rn(b2[i] * 256.0f);
    for (int i = t; i < 16000; i += 256)
        g_f1w[i] = iclamp(__float2int_rn(f1w[i] * 256.0f), QLO, QHI);
    for (int i = t; i < 50; i += 256)
        g_f1b[i] = iclamp(__float2int_rn(f1b[i] * 256.0f), QLO, QHI);
    for (int i = t; i < 500; i += 256)
        g_f2w[i] = iclamp(__float2int_rn(f2w[i] * 256.0f), QLO, QHI);
    for (int i = t; i < 10; i += 256)
        g_f2b[i] = iclamp(__float2int_rn(f2b[i] * 256.0f), QLO, QHI);

    m1 = __reduce_max_sync(0xffffffffu, m1);
    m2 = __reduce_max_sync(0xffffffffu, m2);
    if ((t & 31) == 0) { sm1[t >> 5] = m1; sm2[t >> 5] = m2; }
    __syncthreads();
    if (t == 0) {
        int a = sm1[0], b = sm2[0];
#pragma unroll
        for (int i = 1; i < 8; i++) { a = max(a, sm1[i]); b = max(b, sm2[i]); }
        g_maxw1 = a;
        g_maxw2 = b;
        g_maxx = 0;
        g_maxc1 = 0;
    }
}

// ---------------------------------------------------------------------------
__global__ void __launch_bounds__(256) quantx_kernel(const float4* __restrict__ x,
                                                     float4* __restrict__ out) {
    int i = blockIdx.x * 256 + threadIdx.x;   // exact: 1568*256
    float4 v = x[i];
    int q0 = __float2int_rn(v.x * 256.0f);
    int q1 = __float2int_rn(v.y * 256.0f);
    int q2 = __float2int_rn(v.z * 256.0f);
    int q3 = __float2int_rn(v.w * 256.0f);
    v.x = q0 * 0.00390625f; v.y = q1 * 0.00390625f;
    v.z = q2 * 0.00390625f; v.w = q3 * 0.00390625f;
    out[i] = v;
    int m = max(max(abs(q0), abs(q1)), max(abs(q2), abs(q3)));
    blockAtomicMax<8>(m, &g_maxx);
}

// ---------------------------------------------------------------------------
// conv1 fused with pool1. Thread = (b, co, R): out rows 2R,2R+1 + pooled row R.
// FAST path: f32x2 pairs + IADD3 dual-tap.

__device__ __forceinline__ void c1taps(unsigned* acc, const ull* E, const ull* O,
                                       int wbase) {
    ull w0 = g_w1b[wbase + 0];
    ull w1 = g_w1b[wbase + 1];
    ull w2 = g_w1b[wbase + 2];
    ull w3 = g_w1b[wbase + 3];
    ull w4 = g_w1b[wbase + 4];
#pragma unroll
    for (int k = 0; k < 12; k++) {
        ull y0 = ffma2m(E[k], w0);
        ull y1 = ffma2m(O[k], w1);
        ull y2 = ffma2m(E[k + 1], w2);
        ull y3 = ffma2m(O[k + 1], w3);
        ull y4 = ffma2m(E[k + 2], w4);
        acc[2 * k] = acc[2 * k] + lo32(y0) + lo32(y1);
        acc[2 * k] = acc[2 * k] + lo32(y2) + lo32(y3);
        acc[2 * k] = acc[2 * k] + lo32(y4);
        acc[2 * k + 1] = acc[2 * k + 1] + hi32(y0) + hi32(y1);
        acc[2 * k + 1] = acc[2 * k + 1] + hi32(y2) + hi32(y3);
        acc[2 * k + 1] = acc[2 * k + 1] + hi32(y4);
    }
}

__device__ __forceinline__ void conv1_epilogue(float* dout, int b, int co, int R,
                                               const int* acc0, const int* acc1) {
    float* Ox = dout + OFF_C1OUT + ((b * 10 + co) * 24 + 2 * R) * 24;
#pragma unroll
    for (int j = 0; j < 24; j += 4) {
        float4 v0, v1;
        v0.x = __int2float_rn(acc0[j + 0]) * 0.00390625f;
        v0.y = __int2float_rn(acc0[j + 1]) * 0.00390625f;
        v0.z = __int2float_rn(acc0[j + 2]) * 0.00390625f;
        v0.w = __int2float_rn(acc0[j + 3]) * 0.00390625f;
        v1.x = __int2float_rn(acc1[j + 0]) * 0.00390625f;
        v1.y = __int2float_rn(acc1[j + 1]) * 0.00390625f;
        v1.z = __int2float_rn(acc1[j + 2]) * 0.00390625f;
        v1.w = __int2float_rn(acc1[j + 3]) * 0.00390625f;
        *(float4*)(Ox + j) = v0;
        *(float4*)(Ox + 24 + j) = v1;
    }
    int pc[12];
    int pmax = 0;
#pragma unroll
    for (int j = 0; j < 12; j++) {
        int m = max(max(acc0[2 * j], acc0[2 * j + 1]),
                    max(acc1[2 * j], acc1[2 * j + 1]));
        m = max(m, 0);
        pc[j] = m;
        pmax = max(pmax, m);
    }
    float* P = dout + OFF_C2IN + ((b * 10 + co) * 12 + R) * 12;
#pragma unroll
    for (int j = 0; j < 12; j += 4) {
        float4 v;
        v.x = pc[j + 0] * 0.00390625f;
        v.y = pc[j + 1] * 0.00390625f;
        v.z = pc[j + 2] * 0.00390625f;
        v.w = pc[j + 3] * 0.00390625f;
        *(float4*)(P + j) = v;
    }
    blockAtomicMax<4>(pmax, &g_maxc1);
}

__device__ __forceinline__ void conv1_fast_body(float* __restrict__ dout) {
    int t = blockIdx.x * 128 + threadIdx.x;
    int b = t / 120;
    int r = t % 120;
    int co = r / 12;
    int R = r % 12;

    unsigned bias = (unsigned)g_b1[co] - 25u * MAGICI;
    unsigned acc0[24], acc1[24];
#pragma unroll
    for (int j = 0; j < 24; j++) { acc0[j] = bias; acc1[j] = bias; }

    const float* X = dout + OFF_C1IN + b * 784 + R * 56;
#pragma unroll
    for (int rr = 0; rr < 6; rr++) {
        ull E[14];
        const ulonglong2* xp = (const ulonglong2*)(X + rr * 28);
#pragma unroll
        for (int i = 0; i < 7; i++) {
            ulonglong2 v = xp[i];
            E[2 * i] = v.x;
            E[2 * i + 1] = v.y;
        }
        ull O[13];
#pragma unroll
        for (int i = 0; i < 13; i++) O[i] = mkpack(hi32(E[i]), lo32(E[i + 1]));
        if (rr < 5)  c1taps(acc0, E, O, co * 25 + rr * 5);
        if (rr >= 1) c1taps(acc1, E, O, co * 25 + (rr - 1) * 5);
    }
    conv1_epilogue(dout, b, co, R, (const int*)acc0, (const int*)acc1);
}

// slow clamped scalar path (exact for any input)
__device__ __forceinline__ void conv1_slow_body(float* __restrict__ dout) {
    int t = blockIdx.x * 128 + threadIdx.x;
    int b = t / 120;
    int r = t % 120;
    int co = r / 12;
    int R = r % 12;

    int bq = g_b1[co];
    int acc0[24], acc1[24];
#pragma unroll
    for (int j = 0; j < 24; j++) { acc0[j] = bq; acc1[j] = bq; }

    const float* X = dout + OFF_C1IN + b * 784 + R * 56;
    float xa[28], xb[28];
    loadrow28(xa, X);
    loadrow28(xb, X + 28);
#pragma unroll
    for (int p = 0; p < 5; p++) {
        float wq[5];
#pragma unroll
        for (int i = 0; i < 5; i++) wq[i] = g_w1[co * 25 + p * 5 + i];
#pragma unroll
        for (int q = 0; q < 5; q++) {
            float w = wq[q];
#pragma unroll
            for (int j = 0; j < 24; j++) {
                float y0 = fmaf(xa[j + q], w, MAGICF);
                float y1 = fmaf(xb[j + q], w, MAGICF);
                y0 = fminf(fmaxf(y0, CLAMP_LO), CLAMP_HI);
                y1 = fminf(fmaxf(y1, CLAMP_LO), CLAMP_HI);
                acc0[j] += __float_as_int(y0) - MAGICIi;
                acc1[j] += __float_as_int(y1) - MAGICIi;
            }
        }
        if (p < 4) {
#pragma unroll
            for (int j = 0; j < 28; j++) xa[j] = xb[j];
            loadrow28(xb, X + (p + 2) * 28);
        }
    }
    conv1_epilogue(dout, b, co, R, acc0, acc1);
}

__global__ void __launch_bounds__(128) conv1_kernel(float* __restrict__ dout) {
    bool safe = (long long)g_maxx * (long long)g_maxw1 <= SAFE_BOUND;
    if (safe) conv1_fast_body(dout);
    else      conv1_slow_body(dout);
}

// ---------------------------------------------------------------------------
// conv2: [2048,10,12,12] -> [2048,20,8,8]. Thread = (b, cg of 4 couts, row).

template <bool CONSUME>
__device__ __forceinline__ void c2step(unsigned acc[4][8], ull carry[4][4],
                                       const float* Xrow, int cg, int ci, int p) {
    ull E[6];
    const ulonglong2* xp = (const ulonglong2*)Xrow;
#pragma unroll
    for (int i = 0; i < 3; i++) {
        ulonglong2 v = xp[i];
        E[2 * i] = v.x;
        E[2 * i + 1] = v.y;
    }
    ull O[5];
#pragma unroll
    for (int i = 0; i < 5; i++) O[i] = mkpack(hi32(E[i]), lo32(E[i + 1]));
#pragma unroll
    for (int u = 0; u < 4; u++) {
        const ulonglong2* wp =
            (const ulonglong2*)(g_w2b + (((cg * 4 + u) * 10 + ci) * 5 + p) * 6);
        ulonglong2 wa = wp[0];
        ulonglong2 wb = wp[1];
        ulonglong2 wc = wp[2];
#pragma unroll
        for (int k = 0; k < 4; k++) {
            ull y0 = ffma2m(E[k], wa.x);
            ull y1 = ffma2m(O[k], wa.y);
            ull y2 = ffma2m(E[k + 1], wb.x);
            ull y3 = ffma2m(O[k + 1], wb.y);
            ull y4 = ffma2m(E[k + 2], wc.x);
            acc[u][2 * k] = acc[u][2 * k] + lo32(y0) + lo32(y1);
            acc[u][2 * k] = acc[u][2 * k] + lo32(y2) + lo32(y3);
            acc[u][2 * k + 1] = acc[u][2 * k + 1] + hi32(y0) + hi32(y1);
            acc[u][2 * k + 1] = acc[u][2 * k + 1] + hi32(y2) + hi32(y3);
            if (CONSUME) {
                acc[u][2 * k]     = acc[u][2 * k]     + lo32(y4) + lo32(carry[u][k]);
                acc[u][2 * k + 1] = acc[u][2 * k + 1] + hi32(y4) + hi32(carry[u][k]);
            } else {
                carry[u][k] = y4;
            }
        }
    }
}

__device__ __forceinline__ void conv2_fast_body(float* __restrict__ dout) {
    int t = blockIdx.x * 128 + threadIdx.x; // 81,920
    int b = t / 40;
    int r = t % 40;
    int cg = r / 8;
    int row = r % 8;

    unsigned acc[4][8];
#pragma unroll
    for (int u = 0; u < 4; u++) {
        unsigned bias = (unsigned)g_b2[cg * 4 + u] - 250u * MAGICI;
#pragma unroll
        for (int j = 0; j < 8; j++) acc[u][j] = bias;
    }
    ull carry[4][4];

    const float* X = dout + OFF_C2IN + b * 1440;
    for (int cc = 0; cc < 5; cc++) {
        int ci0 = 2 * cc;
        // step parity: global index ci*5+p; ci0*5 is even -> pattern below
#pragma unroll
        for (int half = 0; half < 2; half++) {
            int ci = ci0 + half;
            const float* Xc = X + ci * 144 + row * 12;
            if (half == 0) {
                c2step<false>(acc, carry, Xc + 0 * 12, cg, ci, 0);
                c2step<true >(acc, carry, Xc + 1 * 12, cg, ci, 1);
                c2step<false>(acc, carry, Xc + 2 * 12, cg, ci, 2);
                c2step<true >(acc, carry, Xc + 3 * 12, cg, ci, 3);
                c2step<false>(acc, carry, Xc + 4 * 12, cg, ci, 4);
            } else {
                c2step<true >(acc, carry, Xc + 0 * 12, cg, ci, 0);
                c2step<false>(acc, carry, Xc + 1 * 12, cg, ci, 1);
                c2step<true >(acc, carry, Xc + 2 * 12, cg, ci, 2);
                c2step<false>(acc, carry, Xc + 3 * 12, cg, ci, 3);
                c2step<true >(acc, carry, Xc + 4 * 12, cg, ci, 4);
            }
        }
    }

#pragma unroll
    for (int u = 0; u < 4; u++) {
        float* O = dout + OFF_C2OUT + ((b * 20 + cg * 4 + u) * 8 + row) * 8;
#pragma unroll
        for (int j = 0; j < 8; j += 4) {
            float4 v;
            v.x = __int2float_rn((int)acc[u][j + 0]) * 0.00390625f;
            v.y = __int2float_rn((int)acc[u][j + 1]) * 0.00390625f;
            v.z = __int2float_rn((int)acc[u][j + 2]) * 0.00390625f;
            v.w = __int2float_rn((int)acc[u][j + 3]) * 0.00390625f;
            *(float4*)(O + j) = v;
        }
    }
}

__device__ __forceinline__ void conv2_slow_body(float* __restrict__ dout) {
    int t = blockIdx.x * 128 + threadIdx.x;
    int b = t / 40;
    int r = t % 40;
    int cg = r / 8;
    int row = r % 8;

    int acc[4][8];
#pragma unroll
    for (int u = 0; u < 4; u++) {
        int bq = g_b2[cg * 4 + u];
#pragma unroll
        for (int j = 0; j < 8; j++) acc[u][j] = bq;
    }

    const float* X = dout + OFF_C2IN + b * 1440;
    for (int ci = 0; ci < 10; ci++) {
        for (int p = 0; p < 5; p++) {
            float xr[12];
            const float4* xp = (const float4*)(X + ci * 144 + (row + p) * 12);
#pragma unroll
            for (int i = 0; i < 3; i++) {
                float4 v = xp[i];
                xr[4 * i + 0] = v.x; xr[4 * i + 1] = v.y;
                xr[4 * i + 2] = v.z; xr[4 * i + 3] = v.w;
            }
#pragma unroll
            for (int u = 0; u < 4; u++) {
                const float* wp = &g_w2p[(((cg * 4 + u) * 10 + ci) * 5 + p) * 8];
                float4 w03 = *(const float4*)wp;
                float wq[5] = {w03.x, w03.y, w03.z, w03.w, wp[4]};
#pragma unroll
                for (int q = 0; q < 5; q++) {
                    float w = wq[q];
#pragma unroll
                    for (int j = 0; j < 8; j++) {
                        float y = fmaf(xr[j + q], w, MAGICF);
                        y = fminf(fmaxf(y, CLAMP_LO), CLAMP_HI);
                        acc[u][j] += __float_as_int(y) - MAGICIi;
                    }
                }
            }
        }
    }

#pragma unroll
    for (int u = 0; u < 4; u++) {
        float* O = dout + OFF_C2OUT + ((b * 20 + cg * 4 + u) * 8 + row) * 8;
#pragma unroll
        for (int j = 0; j < 8; j += 4) {
            float4 v;
            v.x = __int2float_rn(acc[u][j + 0]) * 0.00390625f;
            v.y = __int2float_rn(acc[u][j + 1]) * 0.00390625f;
            v.z = __int2float_rn(acc[u][j + 2]) * 0.00390625f;
            v.w = __int2float_rn(acc[u][j + 3]) * 0.00390625f;
            *(float4*)(O + j) = v;
        }
    }
}

__global__ void __launch_bounds__(128) conv2_kernel(float* __restrict__ dout) {
    bool safe = (long long)g_maxc1 * (long long)g_maxw2 <= SAFE_BOUND;
    if (safe) conv2_fast_body(dout);
    else      conv2_slow_body(dout);
}

// ---------------------------------------------------------------------------
__global__ void __launch_bounds__(256) pool_kernel(const float* __restrict__ src,
                                                   float* __restrict__ dst,
                                                   int n, int W) {
    int i = blockIdx.x * 256 + threadIdx.x;
    if (i >= n) return;
    int c = i / (W * W);
    int rem = i % (W * W);
    int r = rem / W;
    int col = rem % W;
    int W2 = 2 * W;
    const float* base = src + c * (4 * W * W) + (2 * r) * W2 + 2 * col;
    float2 a = *(const float2*)base;
    float2 d = *(const float2*)(base + W2);
    float m = fmaxf(fmaxf(a.x, a.y), fmaxf(d.x, d.y));
    dst[i] = fmaxf(m, 0.0f);
}

// ---------------------------------------------------------------------------
__global__ void __launch_bounds__(128) fc_kernel(float* __restrict__ dout) {
    __shared__ int   xq[2][320];
    __shared__ int   x2[2][64];
    __shared__ float v2[2][16];

    int sub = threadIdx.x >> 6;
    int lane = threadIdx.x & 63;
    int rowI = blockIdx.x * 2 + sub;

    const float* xin = dout + OFF_FC1IN + rowI * 320;
    for (int k = lane; k < 320; k += 64) {
        int q = __float2int_rn(xin[k] * 256.0f);
        xq[sub][k] = iclamp(q, QLO, QHI);
    }
    __syncthreads();

    if (lane < 50) {
        int S = g_f1b[lane] << 8;
        const int* w = &g_f1w[lane * 320];
#pragma unroll 8
        for (int k = 0; k < 320; k++) S += xq[sub][k] * w[k];
        S = iclamp(S, -524288, 458752);
        int q = rhe8(S);
        float f = q * 0.00390625f;
        dout[OFF_FC1OUT + rowI * 50 + lane] = f;
        int qr = q > 0 ? q : 0;
        dout[OFF_FC2IN + rowI * 50 + lane] = qr * 0.00390625f;
        x2[sub][lane] = qr;
    }
    __syncthreads();

    if (lane < 10) {
        int S = g_f2b[lane] << 8;
        const int* w = &g_f2w[lane * 50];
#pragma unroll
        for (int k = 0; k < 50; k++) S += x2[sub][k] * w[k];
        S = iclamp(S, -524288, 458752);
        int q = rhe8(S);
        float f = q * 0.00390625f;
        dout[OFF_FC2OUT + rowI * 10 + lane] = f;
        v2[sub][lane] = f;
    }
    __syncthreads();

    if (lane < 10) {
        float m = -1e30f;
#pragma unroll
        for (int k = 0; k < 10; k++) m = fmaxf(m, v2[sub][k]);
        float s = 0.0f;
#pragma unroll
        for (int k = 0; k < 10; k++) s += expf(v2[sub][k] - m);
        dout[OFF_LOGP + rowI * 10 + lane] = v2[sub][lane] - m - logf(s);
    }
}

// ---------------------------------------------------------------------------
extern "C" void kernel_launch(void* const* d_in, const int* in_sizes, int n_in,
                              void* d_out, int out_size) {
    const float* x   = (const float*)d_in[0];
    const float* w1  = (const float*)d_in[1];
    const float* b1  = (const float*)d_in[2];
    const float* w2  = (const float*)d_in[3];
    const float* b2  = (const float*)d_in[4];
    const float* f1w = (const float*)d_in[5];
    const float* f1b = (const float*)d_in[6];
    const float* f2w = (const float*)d_in[7];
    const float* f2b = (const float*)d_in[8];
    float* out = (float*)d_out;

    prep_kernel<<<1, 256>>>(w1, b1, w2, b2, f1w, f1b, f2w, f2b);
    quantx_kernel<<<1568, 256>>>((const float4*)x, (float4*)(out + OFF_C1IN));
    conv1_kernel<<<1920, 128>>>(out);
    conv2_kernel<<<640, 128>>>(out);
    pool_kernel<<<2560, 256>>>(out + OFF_C2OUT, out + OFF_FC1IN, 655360, 4);
    fc_kernel<<<1024, 128>>>(out);
}

// round 5
// speedup vs baseline: 1.0136x; 1.0136x over previous
#include <cuda_runtime.h>

// ---------------------------------------------------------------------------
// Quantized LeNet, exact fixed-point semantics.
// APREC=8, PPREC=8, IWIDTH=3 -> clamp to [-8.0, +7.0], grid 1/256.
//
// round_half_even(x*w256) == fmaf(x, w256, MAGIC) - MAGIC (MAGIC=1.5*2^23).
// Fast path (clamp provably a no-op): fma.rn.f32x2 rounds TWO pixels per fma
// instruction; IADD3 merges two 32-bit halves per alu op; magic bias removed
// once via acc init = bias - ntaps*MAGICI (exact mod 2^32).
// Clamped scalar fallback behind a uniform branch keeps ANY input exact.
// R5: occupancy-oriented remap (conv1 column halves, conv2 2 couts/thread),
// pool2 fused into fc.
// ---------------------------------------------------------------------------

typedef unsigned long long ull;

#define MAGICF 12582912.0f
#define MAGICI 0x4B400000u
#define MAGICIi 0x4B400000
#define MAGIC2 0x4B4000004B400000ULL
#define CLAMP_LO (MAGICF - 2048.0f)
#define CLAMP_HI (MAGICF + 1792.0f)   // QMAX = +7.0
#define QLO (-2048)
#define QHI 1792
#define SAFE_BOUND 458624             // 1792*256 - 128

#define OFF_LOGP   0
#define OFF_C1IN   20480
#define OFF_C1OUT  1626112
#define OFF_C2IN   13422592
#define OFF_C2OUT  16371712
#define OFF_FC1IN  18993152
#define OFF_FC1OUT 19648512
#define OFF_FC2IN  19750912
#define OFF_FC2OUT 19853312

__device__ float g_w1[256];          // conv1 w*256 scalar
__device__ ull   g_w1b[256];         // conv1 broadcast pairs (w,w)
__device__ int   g_b1[16];
__device__ float g_w2p[8000];        // conv2 scalar, [20][10][5][8]
__device__ ull   g_w2b[6016];        // conv2 broadcast pairs, [20][10][5][6]
__device__ int   g_b2[32];
__device__ int   g_f1w[16000];
__device__ int   g_f1b[64];
__device__ int   g_f2w[512];
__device__ int   g_f2b[16];
__device__ int   g_maxx;
__device__ int   g_maxc1;
__device__ int   g_maxw1;
__device__ int   g_maxw2;

__device__ __forceinline__ int iclamp(int v, int lo, int hi) {
    return v < lo ? lo : (v > hi ? hi : v);
}
__device__ __forceinline__ int rhe8(int S) {
    return (S + 127 + ((S >> 8) & 1)) >> 8;
}
__device__ __forceinline__ unsigned lo32(ull v) { return (unsigned)v; }
__device__ __forceinline__ unsigned hi32(ull v) { return (unsigned)(v >> 32); }
__device__ __forceinline__ ull mkpack(unsigned lo, unsigned hi) {
    ull d;
    asm("mov.b64 %0, {%1, %2};" : "=l"(d) : "r"(lo), "r"(hi));
    return d;
}
__device__ __forceinline__ ull ffma2m(ull x, ull w) {
    ull d;
    ull m = MAGIC2;
    asm("fma.rn.f32x2 %0, %1, %2, %3;" : "=l"(d) : "l"(x), "l"(w), "l"(m));
    return d;
}

template <int NW>
__device__ __forceinline__ void blockAtomicMax(int v, int* dst) {
    __shared__ int sm[NW];
    v = __reduce_max_sync(0xffffffffu, v);
    int w = threadIdx.x >> 5;
    if ((threadIdx.x & 31) == 0) sm[w] = v;
    __syncthreads();
    if (threadIdx.x == 0) {
        int m = sm[0];
#pragma unroll
        for (int i = 1; i < NW; i++) m = max(m, sm[i]);
        atomicMax(dst, m);
    }
}

// ---------------------------------------------------------------------------
__global__ void prep_kernel(const float* __restrict__ w1, const float* __restrict__ b1,
                            const float* __restrict__ w2, const float* __restrict__ b2,
                            const float* __restrict__ f1w, const float* __restrict__ f1b,
                            const float* __restrict__ f2w, const float* __restrict__ f2b) {
    __shared__ int sm1[8], sm2[8];
    int t = threadIdx.x;
    int m1 = 0, m2 = 0;
    for (int i = t; i < 250; i += 256) {
        float q = rintf(w1[i] * 256.0f);
        g_w1[i] = q;
        unsigned u = __float_as_uint(q);
        g_w1b[i] = ((ull)u << 32) | u;
        m1 = max(m1, abs((int)q));
    }
    for (int i = t; i < 10; i += 256) g_b1[i] = __float2int_rn(b1[i] * 256.0f);
    for (int i = t; i < 8000; i += 256) {
        int q = i & 7;
        int rest = i >> 3;
        int p = rest % 5;
        int cc = rest / 5;
        int cin = cc % 10;
        int cout = cc / 10;
        float v = 0.0f;
        if (q < 5) {
            v = rintf(w2[((cout * 10 + cin) * 5 + p) * 5 + q] * 256.0f);
            m2 = max(m2, abs((int)v));
        }
        g_w2p[i] = v;
    }
    for (int i = t; i < 6000; i += 256) {
        int q = i % 6;
        int rest = i / 6;
        int p = rest % 5;
        int cc = rest / 5;
        int cin = cc % 10;
        int cout = cc / 10;
        float v = 0.0f;
        if (q < 5) v = rintf(w2[((cout * 10 + cin) * 5 + p) * 5 + q] * 256.0f);
        unsigned u = __float_as_uint(v);
        g_w2b[i] = ((ull)u << 32) | u;
    }
    for (int i = t; i < 20; i += 256) g_b2[i] = __float2int_rn(b2[i] * 256.0f);
    for (int i = t; i < 16000; i += 256)
        g_f1w[i] = iclamp(__float2int_rn(f1w[i] * 256.0f), QLO, QHI);
    for (int i = t; i < 50; i += 256)
        g_f1b[i] = iclamp(__float2int_rn(f1b[i] * 256.0f), QLO, QHI);
    for (int i = t; i < 500; i += 256)
        g_f2w[i] = iclamp(__float2int_rn(f2w[i] * 256.0f), QLO, QHI);
    for (int i = t; i < 10; i += 256)
        g_f2b[i] = iclamp(__float2int_rn(f2b[i] * 256.0f), QLO, QHI);

    m1 = __reduce_max_sync(0xffffffffu, m1);
    m2 = __reduce_max_sync(0xffffffffu, m2);
    if ((t & 31) == 0) { sm1[t >> 5] = m1; sm2[t >> 5] = m2; }
    __syncthreads();
    if (t == 0) {
        int a = sm1[0], b = sm2[0];
#pragma unroll
        for (int i = 1; i < 8; i++) { a = max(a, sm1[i]); b = max(b, sm2[i]); }
        g_maxw1 = a;
        g_maxw2 = b;
        g_maxx = 0;
        g_maxc1 = 0;
    }
}

// ---------------------------------------------------------------------------
__global__ void __launch_bounds__(256) quantx_kernel(const float4* __restrict__ x,
                                                     float4* __restrict__ out) {
    int i = blockIdx.x * 256 + threadIdx.x;   // exact: 1568*256
    float4 v = x[i];
    int q0 = __float2int_rn(v.x * 256.0f);
    int q1 = __float2int_rn(v.y * 256.0f);
    int q2 = __float2int_rn(v.z * 256.0f);
    int q3 = __float2int_rn(v.w * 256.0f);
    v.x = q0 * 0.00390625f; v.y = q1 * 0.00390625f;
    v.z = q2 * 0.00390625f; v.w = q3 * 0.00390625f;
    out[i] = v;
    int m = max(max(abs(q0), abs(q1)), max(abs(q2), abs(q3)));
    blockAtomicMax<8>(m, &g_maxx);
}

// ---------------------------------------------------------------------------
// conv1 fused with pool1, COLUMN-HALVED for occupancy.
// Thread = (b, co, R, h): conv1_out rows 2R,2R+1 cols [12h,12h+12),
// pooled row R cols [6h,6h+6).  491,520 threads = 3840 blocks * 128.

__device__ __forceinline__ void c1taps6(unsigned* acc, const ull* E, const ull* O,
                                        int wbase) {
    ull w0 = g_w1b[wbase + 0];
    ull w1 = g_w1b[wbase + 1];
    ull w2 = g_w1b[wbase + 2];
    ull w3 = g_w1b[wbase + 3];
    ull w4 = g_w1b[wbase + 4];
#pragma unroll
    for (int k = 0; k < 6; k++) {
        ull y0 = ffma2m(E[k], w0);
        ull y1 = ffma2m(O[k], w1);
        ull y2 = ffma2m(E[k + 1], w2);
        ull y3 = ffma2m(O[k + 1], w3);
        ull y4 = ffma2m(E[k + 2], w4);
        acc[2 * k] = acc[2 * k] + lo32(y0) + lo32(y1);
        acc[2 * k] = acc[2 * k] + lo32(y2) + lo32(y3);
        acc[2 * k] = acc[2 * k] + lo32(y4);
        acc[2 * k + 1] = acc[2 * k + 1] + hi32(y0) + hi32(y1);
        acc[2 * k + 1] = acc[2 * k + 1] + hi32(y2) + hi32(y3);
        acc[2 * k + 1] = acc[2 * k + 1] + hi32(y4);
    }
}

__device__ __forceinline__ void conv1_epilogue(float* dout, int b, int co, int R,
                                               int h, const int* acc0,
                                               const int* acc1) {
    float* Ox = dout + OFF_C1OUT + ((b * 10 + co) * 24 + 2 * R) * 24 + 12 * h;
#pragma unroll
    for (int j = 0; j < 12; j += 4) {
        float4 v0, v1;
        v0.x = __int2float_rn(acc0[j + 0]) * 0.00390625f;
        v0.y = __int2float_rn(acc0[j + 1]) * 0.00390625f;
        v0.z = __int2float_rn(acc0[j + 2]) * 0.00390625f;
        v0.w = __int2float_rn(acc0[j + 3]) * 0.00390625f;
        v1.x = __int2float_rn(acc1[j + 0]) * 0.00390625f;
        v1.y = __int2float_rn(acc1[j + 1]) * 0.00390625f;
        v1.z = __int2float_rn(acc1[j + 2]) * 0.00390625f;
        v1.w = __int2float_rn(acc1[j + 3]) * 0.00390625f;
        *(float4*)(Ox + j) = v0;
        *(float4*)(Ox + 24 + j) = v1;
    }
    int pmax = 0;
    float* P = dout + OFF_C2IN + ((b * 10 + co) * 12 + R) * 12 + 6 * h;
#pragma unroll
    for (int j = 0; j < 6; j += 2) {
        int m0 = max(max(acc0[2 * j], acc0[2 * j + 1]),
                     max(acc1[2 * j], acc1[2 * j + 1]));
        int m1 = max(max(acc0[2 * j + 2], acc0[2 * j + 3]),
                     max(acc1[2 * j + 2], acc1[2 * j + 3]));
        m0 = max(m0, 0);
        m1 = max(m1, 0);
        pmax = max(pmax, max(m0, m1));
        float2 v;
        v.x = m0 * 0.00390625f;
        v.y = m1 * 0.00390625f;
        *(float2*)(P + j) = v;
    }
    blockAtomicMax<4>(pmax, &g_maxc1);
}

__device__ __forceinline__ void conv1_fast_body(float* __restrict__ dout) {
    int t = blockIdx.x * 128 + threadIdx.x;
    int b = t / 240;
    int rem = t % 240;
    int co = rem / 24;
    int R = (rem % 24) >> 1;
    int h = t & 1;

    unsigned bias = (unsigned)g_b1[co] - 25u * MAGICI;
    unsigned acc0[12], acc1[12];
#pragma unroll
    for (int j = 0; j < 12; j++) { acc0[j] = bias; acc1[j] = bias; }

    const float* X = dout + OFF_C1IN + b * 784 + R * 56 + 12 * h;
#pragma unroll
    for (int rr = 0; rr < 6; rr++) {
        ull E[8];
        const ulonglong2* xp = (const ulonglong2*)(X + rr * 28);
#pragma unroll
        for (int i = 0; i < 4; i++) {
            ulonglong2 v = xp[i];
            E[2 * i] = v.x;
            E[2 * i + 1] = v.y;
        }
        ull O[7];
#pragma unroll
        for (int i = 0; i < 7; i++) O[i] = mkpack(hi32(E[i]), lo32(E[i + 1]));
        if (rr < 5)  c1taps6(acc0, E, O, co * 25 + rr * 5);
        if (rr >= 1) c1taps6(acc1, E, O, co * 25 + (rr - 1) * 5);
    }
    conv1_epilogue(dout, b, co, R, h, (const int*)acc0, (const int*)acc1);
}

__device__ __forceinline__ void conv1_slow_body(float* __restrict__ dout) {
    int t = blockIdx.x * 128 + threadIdx.x;
    int b = t / 240;
    int rem = t % 240;
    int co = rem / 24;
    int R = (rem % 24) >> 1;
    int h = t & 1;

    int bq = g_b1[co];
    int acc0[12], acc1[12];
#pragma unroll
    for (int j = 0; j < 12; j++) { acc0[j] = bq; acc1[j] = bq; }

    const float* X = dout + OFF_C1IN + b * 784 + R * 56 + 12 * h;
#pragma unroll
    for (int rr = 0; rr < 6; rr++) {
        float xr[16];
#pragma unroll
        for (int i = 0; i < 4; i++) {
            float4 v = ((const float4*)(X + rr * 28))[i];
            xr[4 * i + 0] = v.x; xr[4 * i + 1] = v.y;
            xr[4 * i + 2] = v.z; xr[4 * i + 3] = v.w;
        }
#pragma unroll
        for (int pass = 0; pass < 2; pass++) {
            int p = pass == 0 ? rr : rr - 1;
            if (p < 0 || p > 4) continue;
            int* acc = pass == 0 ? acc0 : acc1;
#pragma unroll
            for (int q = 0; q < 5; q++) {
                float w = g_w1[co * 25 + p * 5 + q];
#pragma unroll
                for (int j = 0; j < 12; j++) {
                    float y = fmaf(xr[j + q], w, MAGICF);
                    y = fminf(fmaxf(y, CLAMP_LO), CLAMP_HI);
                    acc[j] += __float_as_int(y) - MAGICIi;
                }
            }
        }
    }
    conv1_epilogue(dout, b, co, R, h, acc0, acc1);
}

__global__ void __launch_bounds__(128) conv1_kernel(float* __restrict__ dout) {
    bool safe = (long long)g_maxx * (long long)g_maxw1 <= SAFE_BOUND;
    if (safe) conv1_fast_body(dout);
    else      conv1_slow_body(dout);
}

// ---------------------------------------------------------------------------
// conv2: [2048,10,12,12] -> [2048,20,8,8]. Thread = (b, cout PAIR, row).
// 163,840 threads = 1280 blocks * 128.

template <bool CONSUME>
__device__ __forceinline__ void c2step(unsigned acc[2][8], ull carry[2][4],
                                       const float* Xrow, int co0, int ci, int p) {
    ull E[6];
    const ulonglong2* xp = (const ulonglong2*)Xrow;
#pragma unroll
    for (int i = 0; i < 3; i++) {
        ulonglong2 v = xp[i];
        E[2 * i] = v.x;
        E[2 * i + 1] = v.y;
    }
    ull O[5];
#pragma unroll
    for (int i = 0; i < 5; i++) O[i] = mkpack(hi32(E[i]), lo32(E[i + 1]));
#pragma unroll
    for (int u = 0; u < 2; u++) {
        const ulonglong2* wp =
            (const ulonglong2*)(g_w2b + (((co0 + u) * 10 + ci) * 5 + p) * 6);
        ulonglong2 wa = wp[0];
        ulonglong2 wb = wp[1];
        ulonglong2 wc = wp[2];
#pragma unroll
        for (int k = 0; k < 4; k++) {
            ull y0 = ffma2m(E[k], wa.x);
            ull y1 = ffma2m(O[k], wa.y);
            ull y2 = ffma2m(E[k + 1], wb.x);
            ull y3 = ffma2m(O[k + 1], wb.y);
            ull y4 = ffma2m(E[k + 2], wc.x);
            acc[u][2 * k] = acc[u][2 * k] + lo32(y0) + lo32(y1);
            acc[u][2 * k] = acc[u][2 * k] + lo32(y2) + lo32(y3);
            acc[u][2 * k + 1] = acc[u][2 * k + 1] + hi32(y0) + hi32(y1);
            acc[u][2 * k + 1] = acc[u][2 * k + 1] + hi32(y2) + hi32(y3);
            if (CONSUME) {
                acc[u][2 * k]     = acc[u][2 * k]     + lo32(y4) + lo32(carry[u][k]);
                acc[u][2 * k + 1] = acc[u][2 * k + 1] + hi32(y4) + hi32(carry[u][k]);
            } else {
                carry[u][k] = y4;
            }
        }
    }
}

__device__ __forceinline__ void conv2_fast_body(float* __restrict__ dout) {
    int t = blockIdx.x * 128 + threadIdx.x; // 163,840
    int b = t / 80;
    int r = t % 80;
    int cp = r / 8;        // cout pair 0..9
    int row = r % 8;
    int co0 = cp * 2;

    unsigned acc[2][8];
#pragma unroll
    for (int u = 0; u < 2; u++) {
        unsigned bias = (unsigned)g_b2[co0 + u] - 250u * MAGICI;
#pragma unroll
        for (int j = 0; j < 8; j++) acc[u][j] = bias;
    }
    ull carry[2][4];

    const float* X = dout + OFF_C2IN + b * 1440;
#pragma unroll 1
    for (int ci = 0; ci < 10; ci += 2) {
        const float* Xc = X + ci * 144 + row * 12;
        c2step<false>(acc, carry, Xc + 0 * 12, co0, ci, 0);
        c2step<true >(acc, carry, Xc + 1 * 12, co0, ci, 1);
        c2step<false>(acc, carry, Xc + 2 * 12, co0, ci, 2);
        c2step<true >(acc, carry, Xc + 3 * 12, co0, ci, 3);
        c2step<false>(acc, carry, Xc + 4 * 12, co0, ci, 4);
        const float* Xd = Xc + 144;
        c2step<true >(acc, carry, Xd + 0 * 12, co0, ci + 1, 0);
        c2step<false>(acc, carry, Xd + 1 * 12, co0, ci + 1, 1);
        c2step<true >(acc, carry, Xd + 2 * 12, co0, ci + 1, 2);
        c2step<false>(acc, carry, Xd + 3 * 12, co0, ci + 1, 3);
        c2step<true >(acc, carry, Xd + 4 * 12, co0, ci + 1, 4);
    }

#pragma unroll
    for (int u = 0; u < 2; u++) {
        float* O = dout + OFF_C2OUT + ((b * 20 + co0 + u) * 8 + row) * 8;
#pragma unroll
        for (int j = 0; j < 8; j += 4) {
            float4 v;
            v.x = __int2float_rn((int)acc[u][j + 0]) * 0.00390625f;
            v.y = __int2float_rn((int)acc[u][j + 1]) * 0.00390625f;
            v.z = __int2float_rn((int)acc[u][j + 2]) * 0.00390625f;
            v.w = __int2float_rn((int)acc[u][j + 3]) * 0.00390625f;
            *(float4*)(O + j) = v;
        }
    }
}

__device__ __forceinline__ void conv2_slow_body(float* __restrict__ dout) {
    int t = blockIdx.x * 128 + threadIdx.x;
    int b = t / 80;
    int r = t % 80;
    int cp = r / 8;
    int row = r % 8;
    int co0 = cp * 2;

    int acc[2][8];
#pragma unroll
    for (int u = 0; u < 2; u++) {
        int bq = g_b2[co0 + u];
#pragma unroll
        for (int j = 0; j < 8; j++) acc[u][j] = bq;
    }

    const float* X = dout + OFF_C2IN + b * 1440;
    for (int ci = 0; ci < 10; ci++) {
        for (int p = 0; p < 5; p++) {
            float xr[12];
            const float4* xp = (const float4*)(X + ci * 144 + (row + p) * 12);
#pragma unroll
            for (int i = 0; i < 3; i++) {
                float4 v = xp[i];
                xr[4 * i + 0] = v.x; xr[4 * i + 1] = v.y;
                xr[4 * i + 2] = v.z; xr[4 * i + 3] = v.w;
            }
#pragma unroll
            for (int u = 0; u < 2; u++) {
                const float* wp = &g_w2p[(((co0 + u) * 10 + ci) * 5 + p) * 8];
                float4 w03 = *(const float4*)wp;
                float wq[5] = {w03.x, w03.y, w03.z, w03.w, wp[4]};
#pragma unroll
                for (int q = 0; q < 5; q++) {
                    float w = wq[q];
#pragma unroll
                    for (int j = 0; j < 8; j++) {
                        float y = fmaf(xr[j + q], w, MAGICF);
                        y = fminf(fmaxf(y, CLAMP_LO), CLAMP_HI);
                        acc[u][j] += __float_as_int(y) - MAGICIi;
                    }
                }
            }
        }
    }

#pragma unroll
    for (int u = 0; u < 2; u++) {
        float* O = dout + OFF_C2OUT + ((b * 20 + co0 + u) * 8 + row) * 8;
#pragma unroll
        for (int j = 0; j < 8; j += 4) {
            float4 v;
            v.x = __int2float_rn(acc[u][j + 0]) * 0.00390625f;
            v.y = __int2float_rn(acc[u][j + 1]) * 0.00390625f;
            v.z = __int2float_rn(acc[u][j + 2]) * 0.00390625f;
            v.w = __int2float_rn(acc[u][j + 3]) * 0.00390625f;
            *(float4*)(O + j) = v;
        }
    }
}

__global__ void __launch_bounds__(128) conv2_kernel(float* __restrict__ dout) {
    bool safe = (long long)g_maxc1 * (long long)g_maxw2 <= SAFE_BOUND;
    if (safe) conv2_fast_body(dout);
    else      conv2_slow_body(dout);
}

// ---------------------------------------------------------------------------
// fused: pool2(relu(maxpool)) -> fc1_input write -> FC1 -> relu -> FC2 ->
// log_softmax. 2 batch rows per 128-thread block.
__global__ void __launch_bounds__(128) fc_kernel(float* __restrict__ dout) {
    __shared__ int   xq[2][320];
    __shared__ int   x2[2][64];
    __shared__ float v2[2][16];

    int sub = threadIdx.x >> 6;
    int lane = threadIdx.x & 63;
    int rowI = blockIdx.x * 2 + sub;

    // pool2 from conv2_output (image = 20ch x 8x8), write fc1_input + smem
    const float* c2o = dout + OFF_C2OUT + rowI * 1280;
    float* f1in = dout + OFF_FC1IN + rowI * 320;
    for (int k = lane; k < 320; k += 64) {
        int c = k >> 4;
        int rem = k & 15;
        int r = rem >> 2;
        int col = rem & 3;
        const float* base = c2o + c * 64 + 2 * r * 8 + 2 * col;
        float2 a = *(const float2*)base;
        float2 d = *(const float2*)(base + 8);
        float m = fmaxf(fmaxf(a.x, a.y), fmaxf(d.x, d.y));
        m = fmaxf(m, 0.0f);
        f1in[k] = m;
        int q = __float2int_rn(m * 256.0f);
        xq[sub][k] = iclamp(q, QLO, QHI);
    }
    __syncthreads();

    if (lane < 50) {
        int S = g_f1b[lane] << 8;
        const int* w = &g_f1w[lane * 320];
#pragma unroll 8
        for (int k = 0; k < 320; k++) S += xq[sub][k] * w[k];
        S = iclamp(S, -524288, 458752);
        int q = rhe8(S);
        float f = q * 0.00390625f;
        dout[OFF_FC1OUT + rowI * 50 + lane] = f;
        int qr = q > 0 ? q : 0;
        dout[OFF_FC2IN + rowI * 50 + lane] = qr * 0.00390625f;
        x2[sub][lane] = qr;
    }
    __syncthreads();

    if (lane < 10) {
        int S = g_f2b[lane] << 8;
        const int* w = &g_f2w[lane * 50];
#pragma unroll
        for (int k = 0; k < 50; k++) S += x2[sub][k] * w[k];
        S = iclamp(S, -524288, 458752);
        int q = rhe8(S);
        float f = q * 0.00390625f;
        dout[OFF_FC2OUT + rowI * 10 + lane] = f;
        v2[sub][lane] = f;
    }
    __syncthreads();

    if (lane < 10) {
        float m = -1e30f;
#pragma unroll
        for (int k = 0; k < 10; k++) m = fmaxf(m, v2[sub][k]);
        float s = 0.0f;
#pragma unroll
        for (int k = 0; k < 10; k++) s += expf(v2[sub][k] - m);
        dout[OFF_LOGP + rowI * 10 + lane] = v2[sub][lane] - m - logf(s);
    }
}

// ---------------------------------------------------------------------------
extern "C" void kernel_launch(void* const* d_in, const int* in_sizes, int n_in,
                              void* d_out, int out_size) {
    const float* x   = (const float*)d_in[0];
    const float* w1  = (const float*)d_in[1];
    const float* b1  = (const float*)d_in[2];
    const float* w2  = (const float*)d_in[3];
    const float* b2  = (const float*)d_in[4];
    const float* f1w = (const float*)d_in[5];
    const float* f1b = (const float*)d_in[6];
    const float* f2w = (const float*)d_in[7];
    const float* f2b = (const float*)d_in[8];
    float* out = (float*)d_out;

    prep_kernel<<<1, 256>>>(w1, b1, w2, b2, f1w, f1b, f2w, f2b);
    quantx_kernel<<<1568, 256>>>((const float4*)x, (float4*)(out + OFF_C1IN));
    conv1_kernel<<<3840, 128>>>(out);
    conv2_kernel<<<1280, 128>>>(out);
    fc_kernel<<<1024, 128>>>(out);
}

// round 6
// speedup vs baseline: 1.0654x; 1.0511x over previous
#include <cuda_runtime.h>

// ---------------------------------------------------------------------------
// Quantized LeNet, exact fixed-point semantics.
// APREC=8, PPREC=8, IWIDTH=3 -> clamp to [-8.0, +7.0], grid 1/256.
//
// round_half_even(x*w256) == fmaf(x, w256, MAGIC) - MAGIC (MAGIC=1.5*2^23).
// Fast path (per-block proof that the clamp is a no-op):
//   fma.rn.f32x2 rounds TWO pixels per fma instruction; IADD3 merges two
//   32-bit halves per alu op; magic bias removed once via
//   acc init = bias - ntaps*MAGICI (exact mod 2^32).
// Clamped scalar fallback per block keeps ANY input exact.
// R6: all conv operands in shared memory (R5 was L1-wavefront-bound),
// quantx fused into conv1, per-block fast/slow decision.
// ---------------------------------------------------------------------------

typedef unsigned long long ull;

#define MAGICF 12582912.0f
#define MAGICI 0x4B400000u
#define MAGICIi 0x4B400000
#define MAGIC2 0x4B4000004B400000ULL
#define CLAMP_LO (MAGICF - 2048.0f)
#define CLAMP_HI (MAGICF + 1792.0f)   // QMAX = +7.0
#define QLO (-2048)
#define QHI 1792
#define SAFE_BOUND 458624             // 1792*256 - 128

#define OFF_LOGP   0
#define OFF_C1IN   20480
#define OFF_C1OUT  1626112
#define OFF_C2IN   13422592
#define OFF_C2OUT  16371712
#define OFF_FC1IN  18993152
#define OFF_FC1OUT 19648512
#define OFF_FC2IN  19750912
#define OFF_FC2OUT 19853312

__device__ ull   g_w1b[256];         // conv1 w*256 broadcast pairs (w,w)
__device__ int   g_b1[16];
__device__ ull   g_w2b[6016];        // conv2 broadcast pairs, [20][10][5][6]
__device__ int   g_b2[32];
__device__ int   g_f1w[16000];
__device__ int   g_f1b[64];
__device__ int   g_f2w[512];
__device__ int   g_f2b[16];
__device__ int   g_maxw1;
__device__ int   g_maxw2;

__device__ __forceinline__ int iclamp(int v, int lo, int hi) {
    return v < lo ? lo : (v > hi ? hi : v);
}
__device__ __forceinline__ int rhe8(int S) {
    return (S + 127 + ((S >> 8) & 1)) >> 8;
}
__device__ __forceinline__ unsigned lo32(ull v) { return (unsigned)v; }
__device__ __forceinline__ unsigned hi32(ull v) { return (unsigned)(v >> 32); }
__device__ __forceinline__ ull mkpack(unsigned lo, unsigned hi) {
    ull d;
    asm("mov.b64 %0, {%1, %2};" : "=l"(d) : "r"(lo), "r"(hi));
    return d;
}
__device__ __forceinline__ ull ffma2m(ull x, ull w) {
    ull d;
    ull m = MAGIC2;
    asm("fma.rn.f32x2 %0, %1, %2, %3;" : "=l"(d) : "l"(x), "l"(w), "l"(m));
    return d;
}

// ---------------------------------------------------------------------------
__global__ void prep_kernel(const float* __restrict__ w1, const float* __restrict__ b1,
                            const float* __restrict__ w2, const float* __restrict__ b2,
                            const float* __restrict__ f1w, const float* __restrict__ f1b,
                            const float* __restrict__ f2w, const float* __restrict__ f2b) {
    __shared__ int sm1[8], sm2[8];
    int t = threadIdx.x;
    int m1 = 0, m2 = 0;
    for (int i = t; i < 250; i += 256) {
        float q = rintf(w1[i] * 256.0f);
        unsigned u = __float_as_uint(q);
        g_w1b[i] = ((ull)u << 32) | u;
        m1 = max(m1, abs((int)q));
    }
    for (int i = t; i < 10; i += 256) g_b1[i] = __float2int_rn(b1[i] * 256.0f);
    for (int i = t; i < 6000; i += 256) {
        int q = i % 6;
        int rest = i / 6;
        int p = rest % 5;
        int cc = rest / 5;            // cout*10 + cin
        int cin = cc % 10;
        int cout = cc / 10;
        float v = 0.0f;
        if (q < 5) {
            v = rintf(w2[((cout * 10 + cin) * 5 + p) * 5 + q] * 256.0f);
            m2 = max(m2, abs((int)v));
        }
        unsigned u = __float_as_uint(v);
        g_w2b[i] = ((ull)u << 32) | u;
    }
    for (int i = t; i < 20; i += 256) g_b2[i] = __float2int_rn(b2[i] * 256.0f);
    for (int i = t; i < 16000; i += 256)
        g_f1w[i] = iclamp(__float2int_rn(f1w[i] * 256.0f), QLO, QHI);
    for (int i = t; i < 50; i += 256)
        g_f1b[i] = iclamp(__float2int_rn(f1b[i] * 256.0f), QLO, QHI);
    for (int i = t; i < 500; i += 256)
        g_f2w[i] = iclamp(__float2int_rn(f2w[i] * 256.0f), QLO, QHI);
    for (int i = t; i < 10; i += 256)
        g_f2b[i] = iclamp(__float2int_rn(f2b[i] * 256.0f), QLO, QHI);

    m1 = __reduce_max_sync(0xffffffffu, m1);
    m2 = __reduce_max_sync(0xffffffffu, m2);
    if ((t & 31) == 0) { sm1[t >> 5] = m1; sm2[t >> 5] = m2; }
    __syncthreads();
    if (t == 0) {
        int a = sm1[0], b = sm2[0];
#pragma unroll
        for (int i = 1; i < 8; i++) { a = max(a, sm1[i]); b = max(b, sm2[i]); }
        g_maxw1 = a;
        g_maxw2 = b;
    }
}

// ---------------------------------------------------------------------------
// conv1 (+ input quant + pool1), one image per 256-thread block.
// Threads 0..239 = (co 0..9, R 0..11, h 0..1): conv1_out rows 2R,2R+1
// cols [12h,12h+12), pooled row R cols [6h,6h+6). x and weights in smem.

__device__ __forceinline__ void c1taps6(unsigned* acc, const ull* E, const ull* O,
                                        const ull* w) {
    ull w0 = w[0];
    ull w1 = w[1];
    ull w2 = w[2];
    ull w3 = w[3];
    ull w4 = w[4];
#pragma unroll
    for (int k = 0; k < 6; k++) {
        ull y0 = ffma2m(E[k], w0);
        ull y1 = ffma2m(O[k], w1);
        ull y2 = ffma2m(E[k + 1], w2);
        ull y3 = ffma2m(O[k + 1], w3);
        ull y4 = ffma2m(E[k + 2], w4);
        acc[2 * k] = acc[2 * k] + lo32(y0) + lo32(y1);
        acc[2 * k] = acc[2 * k] + lo32(y2) + lo32(y3);
        acc[2 * k] = acc[2 * k] + lo32(y4);
        acc[2 * k + 1] = acc[2 * k + 1] + hi32(y0) + hi32(y1);
        acc[2 * k + 1] = acc[2 * k + 1] + hi32(y2) + hi32(y3);
        acc[2 * k + 1] = acc[2 * k + 1] + hi32(y4);
    }
}

__device__ __forceinline__ void conv1_epilogue(float* dout, int b, int co, int R,
                                               int h, const int* acc0,
                                               const int* acc1) {
    float* Ox = dout + OFF_C1OUT + ((b * 10 + co) * 24 + 2 * R) * 24 + 12 * h;
#pragma unroll
    for (int j = 0; j < 12; j += 4) {
        float4 v0, v1;
        v0.x = __int2float_rn(acc0[j + 0]) * 0.00390625f;
        v0.y = __int2float_rn(acc0[j + 1]) * 0.00390625f;
        v0.z = __int2float_rn(acc0[j + 2]) * 0.00390625f;
        v0.w = __int2float_rn(acc0[j + 3]) * 0.00390625f;
        v1.x = __int2float_rn(acc1[j + 0]) * 0.00390625f;
        v1.y = __int2float_rn(acc1[j + 1]) * 0.00390625f;
        v1.z = __int2float_rn(acc1[j + 2]) * 0.00390625f;
        v1.w = __int2float_rn(acc1[j + 3]) * 0.00390625f;
        *(float4*)(Ox + j) = v0;
        *(float4*)(Ox + 24 + j) = v1;
    }
    float* P = dout + OFF_C2IN + ((b * 10 + co) * 12 + R) * 12 + 6 * h;
#pragma unroll
    for (int j = 0; j < 6; j += 2) {
        int m0 = max(max(acc0[2 * j], acc0[2 * j + 1]),
                     max(acc1[2 * j], acc1[2 * j + 1]));
        int m1 = max(max(acc0[2 * j + 2], acc0[2 * j + 3]),
                     max(acc1[2 * j + 2], acc1[2 * j + 3]));
        m0 = max(m0, 0);
        m1 = max(m1, 0);
        float2 v;
        v.x = m0 * 0.00390625f;
        v.y = m1 * 0.00390625f;
        *(float2*)(P + j) = v;
    }
}

__global__ void __launch_bounds__(256) conv1_kernel(const float4* __restrict__ xin,
                                                    float* __restrict__ dout) {
    __shared__ __align__(16) float sx[784];
    __shared__ __align__(16) ull sw[250];
    __shared__ int red[8];

    int b = blockIdx.x;
    int t = threadIdx.x;

    // load raw x, quantize (this IS the conv1_input output), stage in smem
    int mx = 0;
    if (t < 196) {
        float4 v = xin[b * 196 + t];
        int q0 = __float2int_rn(v.x * 256.0f);
        int q1 = __float2int_rn(v.y * 256.0f);
        int q2 = __float2int_rn(v.z * 256.0f);
        int q3 = __float2int_rn(v.w * 256.0f);
        v.x = q0 * 0.00390625f; v.y = q1 * 0.00390625f;
        v.z = q2 * 0.00390625f; v.w = q3 * 0.00390625f;
        ((float4*)sx)[t] = v;
        ((float4*)(dout + OFF_C1IN + b * 784))[t] = v;
        mx = max(max(abs(q0), abs(q1)), max(abs(q2), abs(q3)));
    }
    if (t < 250) sw[t] = g_w1b[t];

    mx = __reduce_max_sync(0xffffffffu, mx);
    if ((t & 31) == 0) red[t >> 5] = mx;
    __syncthreads();
    int xmax = red[0];
#pragma unroll
    for (int i = 1; i < 8; i++) xmax = max(xmax, red[i]);
    bool safe = (long long)xmax * (long long)g_maxw1 <= SAFE_BOUND;

    if (t >= 240) return;
    int co = t / 24;
    int rem = t % 24;
    int R = rem >> 1;
    int h = t & 1;
    const float* X = sx + R * 56 + 12 * h;

    if (safe) {
        unsigned bias = (unsigned)g_b1[co] - 25u * MAGICI;
        unsigned acc0[12], acc1[12];
#pragma unroll
        for (int j = 0; j < 12; j++) { acc0[j] = bias; acc1[j] = bias; }
#pragma unroll
        for (int rr = 0; rr < 6; rr++) {
            ull E[8];
            const ulonglong2* xp = (const ulonglong2*)(X + rr * 28);
#pragma unroll
            for (int i = 0; i < 4; i++) {
                ulonglong2 v = xp[i];
                E[2 * i] = v.x;
                E[2 * i + 1] = v.y;
            }
            ull O[7];
#pragma unroll
            for (int i = 0; i < 7; i++) O[i] = mkpack(hi32(E[i]), lo32(E[i + 1]));
            if (rr < 5)  c1taps6(acc0, E, O, sw + co * 25 + rr * 5);
            if (rr >= 1) c1taps6(acc1, E, O, sw + co * 25 + (rr - 1) * 5);
        }
        conv1_epilogue(dout, b, co, R, h, (const int*)acc0, (const int*)acc1);
    } else {
        int bq = g_b1[co];
        int acc0[12], acc1[12];
#pragma unroll
        for (int j = 0; j < 12; j++) { acc0[j] = bq; acc1[j] = bq; }
#pragma unroll
        for (int rr = 0; rr < 6; rr++) {
            float xr[16];
#pragma unroll
            for (int i = 0; i < 4; i++) {
                float4 v = ((const float4*)(X + rr * 28))[i];
                xr[4 * i + 0] = v.x; xr[4 * i + 1] = v.y;
                xr[4 * i + 2] = v.z; xr[4 * i + 3] = v.w;
            }
#pragma unroll
            for (int pass = 0; pass < 2; pass++) {
                int p = pass == 0 ? rr : rr - 1;
                if (p < 0 || p > 4) continue;
                int* acc = pass == 0 ? acc0 : acc1;
#pragma unroll
                for (int q = 0; q < 5; q++) {
                    float w = __uint_as_float(lo32(sw[co * 25 + p * 5 + q]));
#pragma unroll
                    for (int j = 0; j < 12; j++) {
                        float y = fmaf(xr[j + q], w, MAGICF);
                        y = fminf(fmaxf(y, CLAMP_LO), CLAMP_HI);
                        acc[j] += __float_as_int(y) - MAGICIi;
                    }
                }
            }
        }
        conv1_epilogue(dout, b, co, R, h, acc0, acc1);
    }
}

// ---------------------------------------------------------------------------
// conv2: block = 160 threads = (2 images x 10 couts x 8 rows). Grid 2048 =
// (1024 image pairs) x (2 cout groups). Weights (24KB) + x (11.5KB) in smem.

template <bool CONSUME>
__device__ __forceinline__ void c2step(unsigned acc[8], ull carry[4],
                                       const float* Xrow, const ull* wp) {
    ull E[6];
    const ulonglong2* xp = (const ulonglong2*)Xrow;
#pragma unroll
    for (int i = 0; i < 3; i++) {
        ulonglong2 v = xp[i];
        E[2 * i] = v.x;
        E[2 * i + 1] = v.y;
    }
    ull O[5];
#pragma unroll
    for (int i = 0; i < 5; i++) O[i] = mkpack(hi32(E[i]), lo32(E[i + 1]));
    const ulonglong2* wv = (const ulonglong2*)wp;
    ulonglong2 wa = wv[0];
    ulonglong2 wb = wv[1];
    ulonglong2 wc = wv[2];
#pragma unroll
    for (int k = 0; k < 4; k++) {
        ull y0 = ffma2m(E[k], wa.x);
        ull y1 = ffma2m(O[k], wa.y);
        ull y2 = ffma2m(E[k + 1], wb.x);
        ull y3 = ffma2m(O[k + 1], wb.y);
        ull y4 = ffma2m(E[k + 2], wc.x);
        acc[2 * k] = acc[2 * k] + lo32(y0) + lo32(y1);
        acc[2 * k] = acc[2 * k] + lo32(y2) + lo32(y3);
        acc[2 * k + 1] = acc[2 * k + 1] + hi32(y0) + hi32(y1);
        acc[2 * k + 1] = acc[2 * k + 1] + hi32(y2) + hi32(y3);
        if (CONSUME) {
            acc[2 * k]     = acc[2 * k]     + lo32(y4) + lo32(carry[k]);
            acc[2 * k + 1] = acc[2 * k + 1] + hi32(y4) + hi32(carry[k]);
        } else {
            carry[k] = y4;
        }
    }
}

__global__ void __launch_bounds__(160) conv2_kernel(float* __restrict__ dout) {
    __shared__ __align__(16) float sx[2880];
    __shared__ __align__(16) ull sw[3000];
    __shared__ int red[5];

    int blk = blockIdx.x;     // 0..2047
    int ip = blk >> 1;        // image pair index
    int g = blk & 1;          // cout group (couts 10g..10g+9)
    int t = threadIdx.x;

    // stage weights (10 couts, contiguous 3000 ull)
    const ulonglong2* wsrc = (const ulonglong2*)(g_w2b + g * 3000);
    for (int i = t; i < 1500; i += 160) ((ulonglong2*)sw)[i] = wsrc[i];

    // stage x (2 images) + block max of input counts
    const float4* xs = (const float4*)(dout + OFF_C2IN + ip * 2880);
    int mx = 0;
    for (int i = t; i < 720; i += 160) {
        float4 v = xs[i];
        ((float4*)sx)[i] = v;
        int q0 = __float2int_rn(v.x * 256.0f);
        int q1 = __float2int_rn(v.y * 256.0f);
        int q2 = __float2int_rn(v.z * 256.0f);
        int q3 = __float2int_rn(v.w * 256.0f);
        mx = max(mx, max(max(abs(q0), abs(q1)), max(abs(q2), abs(q3))));
    }
    mx = __reduce_max_sync(0xffffffffu, mx);
    if ((t & 31) == 0) red[t >> 5] = mx;
    __syncthreads();
    int xmax = red[0];
#pragma unroll
    for (int i = 1; i < 5; i++) xmax = max(xmax, red[i]);
    bool safe = (long long)xmax * (long long)g_maxw2 <= SAFE_BOUND;

    int img = t / 80;
    int r = t % 80;
    int co_local = r / 8;
    int row = r % 8;
    int co = g * 10 + co_local;
    const float* X = sx + img * 1440;
    const ull* W = sw + co_local * 300;
    int bi = ip * 2 + img;

    if (safe) {
        unsigned acc[8];
        unsigned bias = (unsigned)g_b2[co] - 250u * MAGICI;
#pragma unroll
        for (int j = 0; j < 8; j++) acc[j] = bias;
        ull carry[4];
#pragma unroll 1
        for (int ci2 = 0; ci2 < 5; ci2++) {
            int cA = 2 * ci2;
            const float* Xa = X + cA * 144 + row * 12;
            const ull* Wa = W + cA * 30;
            c2step<false>(acc, carry, Xa + 0 * 12, Wa + 0);
            c2step<true >(acc, carry, Xa + 1 * 12, Wa + 6);
            c2step<false>(acc, carry, Xa + 2 * 12, Wa + 12);
            c2step<true >(acc, carry, Xa + 3 * 12, Wa + 18);
            c2step<false>(acc, carry, Xa + 4 * 12, Wa + 24);
            const float* Xb = Xa + 144;
            const ull* Wb = Wa + 30;
            c2step<true >(acc, carry, Xb + 0 * 12, Wb + 0);
            c2step<false>(acc, carry, Xb + 1 * 12, Wb + 6);
            c2step<true >(acc, carry, Xb + 2 * 12, Wb + 12);
            c2step<false>(acc, carry, Xb + 3 * 12, Wb + 18);
            c2step<true >(acc, carry, Xb + 4 * 12, Wb + 24);
        }
        float* O = dout + OFF_C2OUT + ((bi * 20 + co) * 8 + row) * 8;
#pragma unroll
        for (int j = 0; j < 8; j += 4) {
            float4 v;
            v.x = __int2float_rn((int)acc[j + 0]) * 0.00390625f;
            v.y = __int2float_rn((int)acc[j + 1]) * 0.00390625f;
            v.z = __int2float_rn((int)acc[j + 2]) * 0.00390625f;
            v.w = __int2float_rn((int)acc[j + 3]) * 0.00390625f;
            *(float4*)(O + j) = v;
        }
    } else {
        int acc[8];
        int bq = g_b2[co];
#pragma unroll
        for (int j = 0; j < 8; j++) acc[j] = bq;
#pragma unroll 1
        for (int ci = 0; ci < 10; ci++) {
#pragma unroll
            for (int p = 0; p < 5; p++) {
                float xr[12];
                const float4* xp = (const float4*)(X + ci * 144 + (row + p) * 12);
#pragma unroll
                for (int i = 0; i < 3; i++) {
                    float4 v = xp[i];
                    xr[4 * i + 0] = v.x; xr[4 * i + 1] = v.y;
                    xr[4 * i + 2] = v.z; xr[4 * i + 3] = v.w;
                }
                const ull* wp = W + (ci * 5 + p) * 6;
#pragma unroll
                for (int q = 0; q < 5; q++) {
                    float w = __uint_as_float(lo32(wp[q]));
#pragma unroll
                    for (int j = 0; j < 8; j++) {
                        float y = fmaf(xr[j + q], w, MAGICF);
                        y = fminf(fmaxf(y, CLAMP_LO), CLAMP_HI);
                        acc[j] += __float_as_int(y) - MAGICIi;
                    }
                }
            }
        }
        float* O = dout + OFF_C2OUT + ((bi * 20 + co) * 8 + row) * 8;
#pragma unroll
        for (int j = 0; j < 8; j += 4) {
            float4 v;
            v.x = __int2float_rn(acc[j + 0]) * 0.00390625f;
            v.y = __int2float_rn(acc[j + 1]) * 0.00390625f;
            v.z = __int2float_rn(acc[j + 2]) * 0.00390625f;
            v.w = __int2float_rn(acc[j + 3]) * 0.00390625f;
            *(float4*)(O + j) = v;
        }
    }
}

// ---------------------------------------------------------------------------
// fused: pool2 -> fc1_input -> FC1 -> relu -> FC2 -> log_softmax.
__global__ void __launch_bounds__(128) fc_kernel(float* __restrict__ dout) {
    __shared__ int   xq[2][320];
    __shared__ int   x2[2][64];
    __shared__ float v2[2][16];

    int sub = threadIdx.x >> 6;
    int lane = threadIdx.x & 63;
    int rowI = blockIdx.x * 2 + sub;

    const float* c2o = dout + OFF_C2OUT + rowI * 1280;
    float* f1in = dout + OFF_FC1IN + rowI * 320;
    for (int k = lane; k < 320; k += 64) {
        int c = k >> 4;
        int rem = k & 15;
        int r = rem >> 2;
        int col = rem & 3;
        const float* base = c2o + c * 64 + 2 * r * 8 + 2 * col;
        float2 a = *(const float2*)base;
        float2 d = *(const float2*)(base + 8);
        float m = fmaxf(fmaxf(a.x, a.y), fmaxf(d.x, d.y));
        m = fmaxf(m, 0.0f);
        f1in[k] = m;
        int q = __float2int_rn(m * 256.0f);
        xq[sub][k] = iclamp(q, QLO, QHI);
    }
    __syncthreads();

    if (lane < 50) {
        int S = g_f1b[lane] << 8;
        const int* w = &g_f1w[lane * 320];
#pragma unroll 8
        for (int k = 0; k < 320; k++) S += xq[sub][k] * w[k];
        S = iclamp(S, -524288, 458752);
        int q = rhe8(S);
        float f = q * 0.00390625f;
        dout[OFF_FC1OUT + rowI * 50 + lane] = f;
        int qr = q > 0 ? q : 0;
        dout[OFF_FC2IN + rowI * 50 + lane] = qr * 0.00390625f;
        x2[sub][lane] = qr;
    }
    __syncthreads();

    if (lane < 10) {
        int S = g_f2b[lane] << 8;
        const int* w = &g_f2w[lane * 50];
#pragma unroll
        for (int k = 0; k < 50; k++) S += x2[sub][k] * w[k];
        S = iclamp(S, -524288, 458752);
        int q = rhe8(S);
        float f = q * 0.00390625f;
        dout[OFF_FC2OUT + rowI * 10 + lane] = f;
        v2[sub][lane] = f;
    }
    __syncthreads();

    if (lane < 10) {
        float m = -1e30f;
#pragma unroll
        for (int k = 0; k < 10; k++) m = fmaxf(m, v2[sub][k]);
        float s = 0.0f;
#pragma unroll
        for (int k = 0; k < 10; k++) s += expf(v2[sub][k] - m);
        dout[OFF_LOGP + rowI * 10 + lane] = v2[sub][lane] - m - logf(s);
    }
}

// ---------------------------------------------------------------------------
extern "C" void kernel_launch(void* const* d_in, const int* in_sizes, int n_in,
                              void* d_out, int out_size) {
    const float* x   = (const float*)d_in[0];
    const float* w1  = (const float*)d_in[1];
    const float* b1  = (const float*)d_in[2];
    const float* w2  = (const float*)d_in[3];
    const float* b2  = (const float*)d_in[4];
    const float* f1w = (const float*)d_in[5];
    const float* f1b = (const float*)d_in[6];
    const float* f2w = (const float*)d_in[7];
    const float* f2b = (const float*)d_in[8];
    float* out = (float*)d_out;

    prep_kernel<<<1, 256>>>(w1, b1, w2, b2, f1w, f1b, f2w, f2b);
    conv1_kernel<<<2048, 256>>>((const float4*)x, out);
    conv2_kernel<<<2048, 160>>>(out);
    fc_kernel<<<1024, 128>>>(out);
}

// round 7
// speedup vs baseline: 1.8720x; 1.7571x over previous
#include <cuda_runtime.h>

// ---------------------------------------------------------------------------
// Quantized LeNet, exact fixed-point semantics.
// APREC=8, PPREC=8, IWIDTH=3 -> clamp to [-8.0, +7.0], grid 1/256.
//
// round_half_even(x*w256) == fmaf(x, w256, MAGIC) - MAGIC (MAGIC=1.5*2^23).
// Fast path (per-block proof that the clamp is a no-op):
//   fma.rn.f32x2 rounds TWO pixels per fma instruction; IADD3 merges two
//   32-bit halves per alu op; magic bias removed once via
//   acc init = bias - ntaps*MAGICI (exact mod 2^32).
// Clamped scalar fallback per block keeps ANY input exact.
// R7: fc_kernel rebuilt block-tiled (R6's was global-scatter L1-bound, 122us):
// weights staged coalesced into smem shorts, 16 rows/block.
// ---------------------------------------------------------------------------

typedef unsigned long long ull;

#define MAGICF 12582912.0f
#define MAGICI 0x4B400000u
#define MAGICIi 0x4B400000
#define MAGIC2 0x4B4000004B400000ULL
#define CLAMP_LO (MAGICF - 2048.0f)
#define CLAMP_HI (MAGICF + 1792.0f)   // QMAX = +7.0
#define QLO (-2048)
#define QHI 1792
#define SAFE_BOUND 458624             // 1792*256 - 128

#define OFF_LOGP   0
#define OFF_C1IN   20480
#define OFF_C1OUT  1626112
#define OFF_C2IN   13422592
#define OFF_C2OUT  16371712
#define OFF_FC1IN  18993152
#define OFF_FC1OUT 19648512
#define OFF_FC2IN  19750912
#define OFF_FC2OUT 19853312

__device__ ull   g_w1b[256];         // conv1 w*256 broadcast pairs (w,w)
__device__ int   g_b1[16];
__device__ ull   g_w2b[6016];        // conv2 broadcast pairs, [20][10][5][6]
__device__ int   g_b2[32];
__device__ int   g_f1w[16000];
__device__ int   g_f1b[64];
__device__ int   g_f2w[512];
__device__ int   g_f2b[16];
__device__ int   g_maxw1;
__device__ int   g_maxw2;

__device__ __forceinline__ int iclamp(int v, int lo, int hi) {
    return v < lo ? lo : (v > hi ? hi : v);
}
__device__ __forceinline__ int rhe8(int S) {
    return (S + 127 + ((S >> 8) & 1)) >> 8;
}
__device__ __forceinline__ unsigned lo32(ull v) { return (unsigned)v; }
__device__ __forceinline__ unsigned hi32(ull v) { return (unsigned)(v >> 32); }
__device__ __forceinline__ ull mkpack(unsigned lo, unsigned hi) {
    ull d;
    asm("mov.b64 %0, {%1, %2};" : "=l"(d) : "r"(lo), "r"(hi));
    return d;
}
__device__ __forceinline__ ull ffma2m(ull x, ull w) {
    ull d;
    ull m = MAGIC2;
    asm("fma.rn.f32x2 %0, %1, %2, %3;" : "=l"(d) : "l"(x), "l"(w), "l"(m));
    return d;
}

// ---------------------------------------------------------------------------
__global__ void prep_kernel(const float* __restrict__ w1, const float* __restrict__ b1,
                            const float* __restrict__ w2, const float* __restrict__ b2,
                            const float* __restrict__ f1w, const float* __restrict__ f1b,
                            const float* __restrict__ f2w, const float* __restrict__ f2b) {
    __shared__ int sm1[8], sm2[8];
    int t = threadIdx.x;
    int m1 = 0, m2 = 0;
    for (int i = t; i < 250; i += 256) {
        float q = rintf(w1[i] * 256.0f);
        unsigned u = __float_as_uint(q);
        g_w1b[i] = ((ull)u << 32) | u;
        m1 = max(m1, abs((int)q));
    }
    for (int i = t; i < 10; i += 256) g_b1[i] = __float2int_rn(b1[i] * 256.0f);
    for (int i = t; i < 6000; i += 256) {
        int q = i % 6;
        int rest = i / 6;
        int p = rest % 5;
        int cc = rest / 5;            // cout*10 + cin
        int cin = cc % 10;
        int cout = cc / 10;
        float v = 0.0f;
        if (q < 5) {
            v = rintf(w2[((cout * 10 + cin) * 5 + p) * 5 + q] * 256.0f);
            m2 = max(m2, abs((int)v));
        }
        unsigned u = __float_as_uint(v);
        g_w2b[i] = ((ull)u << 32) | u;
    }
    for (int i = t; i < 20; i += 256) g_b2[i] = __float2int_rn(b2[i] * 256.0f);
    for (int i = t; i < 16000; i += 256)
        g_f1w[i] = iclamp(__float2int_rn(f1w[i] * 256.0f), QLO, QHI);
    for (int i = t; i < 50; i += 256)
        g_f1b[i] = iclamp(__float2int_rn(f1b[i] * 256.0f), QLO, QHI);
    for (int i = t; i < 500; i += 256)
        g_f2w[i] = iclamp(__float2int_rn(f2w[i] * 256.0f), QLO, QHI);
    for (int i = t; i < 10; i += 256)
        g_f2b[i] = iclamp(__float2int_rn(f2b[i] * 256.0f), QLO, QHI);

    m1 = __reduce_max_sync(0xffffffffu, m1);
    m2 = __reduce_max_sync(0xffffffffu, m2);
    if ((t & 31) == 0) { sm1[t >> 5] = m1; sm2[t >> 5] = m2; }
    __syncthreads();
    if (t == 0) {
        int a = sm1[0], b = sm2[0];
#pragma unroll
        for (int i = 1; i < 8; i++) { a = max(a, sm1[i]); b = max(b, sm2[i]); }
        g_maxw1 = a;
        g_maxw2 = b;
    }
}

// ---------------------------------------------------------------------------
// conv1 (+ input quant + pool1), one image per 256-thread block.

__device__ __forceinline__ void c1taps6(unsigned* acc, const ull* E, const ull* O,
                                        const ull* w) {
    ull w0 = w[0];
    ull w1 = w[1];
    ull w2 = w[2];
    ull w3 = w[3];
    ull w4 = w[4];
#pragma unroll
    for (int k = 0; k < 6; k++) {
        ull y0 = ffma2m(E[k], w0);
        ull y1 = ffma2m(O[k], w1);
        ull y2 = ffma2m(E[k + 1], w2);
        ull y3 = ffma2m(O[k + 1], w3);
        ull y4 = ffma2m(E[k + 2], w4);
        acc[2 * k] = acc[2 * k] + lo32(y0) + lo32(y1);
        acc[2 * k] = acc[2 * k] + lo32(y2) + lo32(y3);
        acc[2 * k] = acc[2 * k] + lo32(y4);
        acc[2 * k + 1] = acc[2 * k + 1] + hi32(y0) + hi32(y1);
        acc[2 * k + 1] = acc[2 * k + 1] + hi32(y2) + hi32(y3);
        acc[2 * k + 1] = acc[2 * k + 1] + hi32(y4);
    }
}

__device__ __forceinline__ void conv1_epilogue(float* dout, int b, int co, int R,
                                               int h, const int* acc0,
                                               const int* acc1) {
    float* Ox = dout + OFF_C1OUT + ((b * 10 + co) * 24 + 2 * R) * 24 + 12 * h;
#pragma unroll
    for (int j = 0; j < 12; j += 4) {
        float4 v0, v1;
        v0.x = __int2float_rn(acc0[j + 0]) * 0.00390625f;
        v0.y = __int2float_rn(acc0[j + 1]) * 0.00390625f;
        v0.z = __int2float_rn(acc0[j + 2]) * 0.00390625f;
        v0.w = __int2float_rn(acc0[j + 3]) * 0.00390625f;
        v1.x = __int2float_rn(acc1[j + 0]) * 0.00390625f;
        v1.y = __int2float_rn(acc1[j + 1]) * 0.00390625f;
        v1.z = __int2float_rn(acc1[j + 2]) * 0.00390625f;
        v1.w = __int2float_rn(acc1[j + 3]) * 0.00390625f;
        *(float4*)(Ox + j) = v0;
        *(float4*)(Ox + 24 + j) = v1;
    }
    float* P = dout + OFF_C2IN + ((b * 10 + co) * 12 + R) * 12 + 6 * h;
#pragma unroll
    for (int j = 0; j < 6; j += 2) {
        int m0 = max(max(acc0[2 * j], acc0[2 * j + 1]),
                     max(acc1[2 * j], acc1[2 * j + 1]));
        int m1 = max(max(acc0[2 * j + 2], acc0[2 * j + 3]),
                     max(acc1[2 * j + 2], acc1[2 * j + 3]));
        m0 = max(m0, 0);
        m1 = max(m1, 0);
        float2 v;
        v.x = m0 * 0.00390625f;
        v.y = m1 * 0.00390625f;
        *(float2*)(P + j) = v;
    }
}

__global__ void __launch_bounds__(256) conv1_kernel(const float4* __restrict__ xin,
                                                    float* __restrict__ dout) {
    __shared__ __align__(16) float sx[784];
    __shared__ __align__(16) ull sw[250];
    __shared__ int red[8];

    int b = blockIdx.x;
    int t = threadIdx.x;

    int mx = 0;
    if (t < 196) {
        float4 v = xin[b * 196 + t];
        int q0 = __float2int_rn(v.x * 256.0f);
        int q1 = __float2int_rn(v.y * 256.0f);
        int q2 = __float2int_rn(v.z * 256.0f);
        int q3 = __float2int_rn(v.w * 256.0f);
        v.x = q0 * 0.00390625f; v.y = q1 * 0.00390625f;
        v.z = q2 * 0.00390625f; v.w = q3 * 0.00390625f;
        ((float4*)sx)[t] = v;
        ((float4*)(dout + OFF_C1IN + b * 784))[t] = v;
        mx = max(max(abs(q0), abs(q1)), max(abs(q2), abs(q3)));
    }
    if (t < 250) sw[t] = g_w1b[t];

    mx = __reduce_max_sync(0xffffffffu, mx);
    if ((t & 31) == 0) red[t >> 5] = mx;
    __syncthreads();
    int xmax = red[0];
#pragma unroll
    for (int i = 1; i < 8; i++) xmax = max(xmax, red[i]);
    bool safe = (long long)xmax * (long long)g_maxw1 <= SAFE_BOUND;

    if (t >= 240) return;
    int co = t / 24;
    int rem = t % 24;
    int R = rem >> 1;
    int h = t & 1;
    const float* X = sx + R * 56 + 12 * h;

    if (safe) {
        unsigned bias = (unsigned)g_b1[co] - 25u * MAGICI;
        unsigned acc0[12], acc1[12];
#pragma unroll
        for (int j = 0; j < 12; j++) { acc0[j] = bias; acc1[j] = bias; }
#pragma unroll
        for (int rr = 0; rr < 6; rr++) {
            ull E[8];
            const ulonglong2* xp = (const ulonglong2*)(X + rr * 28);
#pragma unroll
            for (int i = 0; i < 4; i++) {
                ulonglong2 v = xp[i];
                E[2 * i] = v.x;
                E[2 * i + 1] = v.y;
            }
            ull O[7];
#pragma unroll
            for (int i = 0; i < 7; i++) O[i] = mkpack(hi32(E[i]), lo32(E[i + 1]));
            if (rr < 5)  c1taps6(acc0, E, O, sw + co * 25 + rr * 5);
            if (rr >= 1) c1taps6(acc1, E, O, sw + co * 25 + (rr - 1) * 5);
        }
        conv1_epilogue(dout, b, co, R, h, (const int*)acc0, (const int*)acc1);
    } else {
        int bq = g_b1[co];
        int acc0[12], acc1[12];
#pragma unroll
        for (int j = 0; j < 12; j++) { acc0[j] = bq; acc1[j] = bq; }
#pragma unroll
        for (int rr = 0; rr < 6; rr++) {
            float xr[16];
#pragma unroll
            for (int i = 0; i < 4; i++) {
                float4 v = ((const float4*)(X + rr * 28))[i];
                xr[4 * i + 0] = v.x; xr[4 * i + 1] = v.y;
                xr[4 * i + 2] = v.z; xr[4 * i + 3] = v.w;
            }
#pragma unroll
            for (int pass = 0; pass < 2; pass++) {
                int p = pass == 0 ? rr : rr - 1;
                if (p < 0 || p > 4) continue;
                int* acc = pass == 0 ? acc0 : acc1;
#pragma unroll
                for (int q = 0; q < 5; q++) {
                    float w = __uint_as_float(lo32(sw[co * 25 + p * 5 + q]));
#pragma unroll
                    for (int j = 0; j < 12; j++) {
                        float y = fmaf(xr[j + q], w, MAGICF);
                        y = fminf(fmaxf(y, CLAMP_LO), CLAMP_HI);
                        acc[j] += __float_as_int(y) - MAGICIi;
                    }
                }
            }
        }
        conv1_epilogue(dout, b, co, R, h, acc0, acc1);
    }
}

// ---------------------------------------------------------------------------
// conv2: block = 160 threads = (2 images x 10 couts x 8 rows).

template <bool CONSUME>
__device__ __forceinline__ void c2step(unsigned acc[8], ull carry[4],
                                       const float* Xrow, const ull* wp) {
    ull E[6];
    const ulonglong2* xp = (const ulonglong2*)Xrow;
#pragma unroll
    for (int i = 0; i < 3; i++) {
        ulonglong2 v = xp[i];
        E[2 * i] = v.x;
        E[2 * i + 1] = v.y;
    }
    ull O[5];
#pragma unroll
    for (int i = 0; i < 5; i++) O[i] = mkpack(hi32(E[i]), lo32(E[i + 1]));
    const ulonglong2* wv = (const ulonglong2*)wp;
    ulonglong2 wa = wv[0];
    ulonglong2 wb = wv[1];
    ulonglong2 wc = wv[2];
#pragma unroll
    for (int k = 0; k < 4; k++) {
        ull y0 = ffma2m(E[k], wa.x);
        ull y1 = ffma2m(O[k], wa.y);
        ull y2 = ffma2m(E[k + 1], wb.x);
        ull y3 = ffma2m(O[k + 1], wb.y);
        ull y4 = ffma2m(E[k + 2], wc.x);
        acc[2 * k] = acc[2 * k] + lo32(y0) + lo32(y1);
        acc[2 * k] = acc[2 * k] + lo32(y2) + lo32(y3);
        acc[2 * k + 1] = acc[2 * k + 1] + hi32(y0) + hi32(y1);
        acc[2 * k + 1] = acc[2 * k + 1] + hi32(y2) + hi32(y3);
        if (CONSUME) {
            acc[2 * k]     = acc[2 * k]     + lo32(y4) + lo32(carry[k]);
            acc[2 * k + 1] = acc[2 * k + 1] + hi32(y4) + hi32(carry[k]);
        } else {
            carry[k] = y4;
        }
    }
}

__global__ void __launch_bounds__(160) conv2_kernel(float* __restrict__ dout) {
    __shared__ __align__(16) float sx[2880];
    __shared__ __align__(16) ull sw[3000];
    __shared__ int red[5];

    int blk = blockIdx.x;     // 0..2047
    int ip = blk >> 1;        // image pair index
    int g = blk & 1;          // cout group (couts 10g..10g+9)
    int t = threadIdx.x;

    const ulonglong2* wsrc = (const ulonglong2*)(g_w2b + g * 3000);
    for (int i = t; i < 1500; i += 160) ((ulonglong2*)sw)[i] = wsrc[i];

    const float4* xs = (const float4*)(dout + OFF_C2IN + ip * 2880);
    int mx = 0;
    for (int i = t; i < 720; i += 160) {
        float4 v = xs[i];
        ((float4*)sx)[i] = v;
        int q0 = __float2int_rn(v.x * 256.0f);
        int q1 = __float2int_rn(v.y * 256.0f);
        int q2 = __float2int_rn(v.z * 256.0f);
        int q3 = __float2int_rn(v.w * 256.0f);
        mx = max(mx, max(max(abs(q0), abs(q1)), max(abs(q2), abs(q3))));
    }
    mx = __reduce_max_sync(0xffffffffu, mx);
    if ((t & 31) == 0) red[t >> 5] = mx;
    __syncthreads();
    int xmax = red[0];
#pragma unroll
    for (int i = 1; i < 5; i++) xmax = max(xmax, red[i]);
    bool safe = (long long)xmax * (long long)g_maxw2 <= SAFE_BOUND;

    int img = t / 80;
    int r = t % 80;
    int co_local = r / 8;
    int row = r % 8;
    int co = g * 10 + co_local;
    const float* X = sx + img * 1440;
    const ull* W = sw + co_local * 300;
    int bi = ip * 2 + img;

    if (safe) {
        unsigned acc[8];
        unsigned bias = (unsigned)g_b2[co] - 250u * MAGICI;
#pragma unroll
        for (int j = 0; j < 8; j++) acc[j] = bias;
        ull carry[4];
#pragma unroll 1
        for (int ci2 = 0; ci2 < 5; ci2++) {
            int cA = 2 * ci2;
            const float* Xa = X + cA * 144 + row * 12;
            const ull* Wa = W + cA * 30;
            c2step<false>(acc, carry, Xa + 0 * 12, Wa + 0);
            c2step<true >(acc, carry, Xa + 1 * 12, Wa + 6);
            c2step<false>(acc, carry, Xa + 2 * 12, Wa + 12);
            c2step<true >(acc, carry, Xa + 3 * 12, Wa + 18);
            c2step<false>(acc, carry, Xa + 4 * 12, Wa + 24);
            const float* Xb = Xa + 144;
            const ull* Wb = Wa + 30;
            c2step<true >(acc, carry, Xb + 0 * 12, Wb + 0);
            c2step<false>(acc, carry, Xb + 1 * 12, Wb + 6);
            c2step<true >(acc, carry, Xb + 2 * 12, Wb + 12);
            c2step<false>(acc, carry, Xb + 3 * 12, Wb + 18);
            c2step<true >(acc, carry, Xb + 4 * 12, Wb + 24);
        }
        float* O = dout + OFF_C2OUT + ((bi * 20 + co) * 8 + row) * 8;
#pragma unroll
        for (int j = 0; j < 8; j += 4) {
            float4 v;
            v.x = __int2float_rn((int)acc[j + 0]) * 0.00390625f;
            v.y = __int2float_rn((int)acc[j + 1]) * 0.00390625f;
            v.z = __int2float_rn((int)acc[j + 2]) * 0.00390625f;
            v.w = __int2float_rn((int)acc[j + 3]) * 0.00390625f;
            *(float4*)(O + j) = v;
        }
    } else {
        int acc[8];
        int bq = g_b2[co];
#pragma unroll
        for (int j = 0; j < 8; j++) acc[j] = bq;
#pragma unroll 1
        for (int ci = 0; ci < 10; ci++) {
#pragma unroll
            for (int p = 0; p < 5; p++) {
                float xr[12];
                const float4* xp = (const float4*)(X + ci * 144 + (row + p) * 12);
#pragma unroll
                for (int i = 0; i < 3; i++) {
                    float4 v = xp[i];
                    xr[4 * i + 0] = v.x; xr[4 * i + 1] = v.y;
                    xr[4 * i + 2] = v.z; xr[4 * i + 3] = v.w;
                }
                const ull* wp = W + (ci * 5 + p) * 6;
#pragma unroll
                for (int q = 0; q < 5; q++) {
                    float w = __uint_as_float(lo32(wp[q]));
#pragma unroll
                    for (int j = 0; j < 8; j++) {
                        float y = fmaf(xr[j + q], w, MAGICF);
                        y = fminf(fmaxf(y, CLAMP_LO), CLAMP_HI);
                        acc[j] += __float_as_int(y) - MAGICIi;
                    }
                }
            }
        }
        float* O = dout + OFF_C2OUT + ((bi * 20 + co) * 8 + row) * 8;
#pragma unroll
        for (int j = 0; j < 8; j += 4) {
            float4 v;
            v.x = __int2float_rn(acc[j + 0]) * 0.00390625f;
            v.y = __int2float_rn(acc[j + 1]) * 0.00390625f;
            v.z = __int2float_rn(acc[j + 2]) * 0.00390625f;
            v.w = __int2float_rn(acc[j + 3]) * 0.00390625f;
            *(float4*)(O + j) = v;
        }
    }
}

// ---------------------------------------------------------------------------
// fc: block = 256 threads, 16 batch rows. fc1 weights staged in smem shorts.
// pool2 -> fc1_input -> FC1 -> relu -> FC2 -> log_softmax, all fused.
__global__ void __launch_bounds__(256) fc_kernel(float* __restrict__ dout) {
    __shared__ short w1s[50 * 330];     // padded: bank = (5*o + k/2) % 32
    __shared__ short xqs[16 * 320];
    __shared__ int   w2s[500];
    __shared__ short x2s[16 * 50];
    __shared__ float v2s[16 * 10];

    int t = threadIdx.x;
    int blk = blockIdx.x;               // rows blk*16 .. blk*16+15

    // stage fc1 weights (coalesced global read, smem shorts)
    for (int i = t; i < 16000; i += 256) {
        int o = i / 320;
        int k = i % 320;
        w1s[o * 330 + k] = (short)g_f1w[i];
    }
    for (int i = t; i < 500; i += 256) w2s[i] = g_f2w[i];

    // phase 1: pool2 + relu + quant (writes fc1_input)
    for (int i = t; i < 5120; i += 256) {
        int r = i / 320;
        int k = i % 320;
        int rowI = blk * 16 + r;
        int c = k >> 4;
        int rem = k & 15;
        int rr = rem >> 2;
        int col = rem & 3;
        const float* base = dout + OFF_C2OUT + rowI * 1280 + c * 64 + 2 * rr * 8 + 2 * col;
        float2 a = *(const float2*)base;
        float2 d = *(const float2*)(base + 8);
        float m = fmaxf(fmaxf(a.x, a.y), fmaxf(d.x, d.y));
        m = fmaxf(m, 0.0f);
        dout[OFF_FC1IN + rowI * 320 + k] = m;
        int q = __float2int_rn(m * 256.0f);
        xqs[r * 320 + k] = (short)iclamp(q, QLO, QHI);
    }
    __syncthreads();

    // phase 2: FC1. thread = (o = t%50, row quad rq = t/50)
    if (t < 200) {
        int o = t % 50;
        int rq = t / 50;
        int bb = g_f1b[o] << 8;
        int S0 = bb, S1 = bb, S2 = bb, S3 = bb;
        const short* wr = &w1s[o * 330];
        const short* x0 = &xqs[(rq * 4 + 0) * 320];
        const short* x1 = &xqs[(rq * 4 + 1) * 320];
        const short* x2 = &xqs[(rq * 4 + 2) * 320];
        const short* x3 = &xqs[(rq * 4 + 3) * 320];
#pragma unroll 8
        for (int k = 0; k < 320; k++) {
            int w = wr[k];
            S0 += x0[k] * w;
            S1 += x1[k] * w;
            S2 += x2[k] * w;
            S3 += x3[k] * w;
        }
        int Ss[4] = {S0, S1, S2, S3};
#pragma unroll
        for (int j = 0; j < 4; j++) {
            int S = iclamp(Ss[j], -524288, 458752);   // [-8, 7] * 65536
            int q = rhe8(S);
            int rloc = rq * 4 + j;
            int rowI = blk * 16 + rloc;
            float f = q * 0.00390625f;
            dout[OFF_FC1OUT + rowI * 50 + o] = f;
            int qr = q > 0 ? q : 0;
            dout[OFF_FC2IN + rowI * 50 + o] = qr * 0.00390625f;
            x2s[rloc * 50 + o] = (short)qr;
        }
    }
    __syncthreads();

    // phase 3: FC2 (160 dots of length 50)
    if (t < 160) {
        int r = t / 10;
        int o = t % 10;
        int S = g_f2b[o] << 8;
        const int* w = &w2s[o * 50];
        const short* xx = &x2s[r * 50];
#pragma unroll
        for (int k = 0; k < 50; k++) S += xx[k] * w[k];
        S = iclamp(S, -524288, 458752);
        int q = rhe8(S);
        float f = q * 0.00390625f;
        int rowI = blk * 16 + r;
        dout[OFF_FC2OUT + rowI * 10 + o] = f;
        v2s[r * 10 + o] = f;
    }
    __syncthreads();

    // phase 4: log_softmax
    if (t < 160) {
        int r = t / 10;
        int o = t % 10;
        const float* v = &v2s[r * 10];
        float m = v[0];
#pragma unroll
        for (int k = 1; k < 10; k++) m = fmaxf(m, v[k]);
        float s = 0.0f;
#pragma unroll
        for (int k = 0; k < 10; k++) s += expf(v[k] - m);
        int rowI = blk * 16 + r;
        dout[OFF_LOGP + rowI * 10 + o] = v[o] - m - logf(s);
    }
}

// ---------------------------------------------------------------------------
extern "C" void kernel_launch(void* const* d_in, const int* in_sizes, int n_in,
                              void* d_out, int out_size) {
    const float* x   = (const float*)d_in[0];
    const float* w1  = (const float*)d_in[1];
    const float* b1  = (const float*)d_in[2];
    const float* w2  = (const float*)d_in[3];
    const float* b2  = (const float*)d_in[4];
    const float* f1w = (const float*)d_in[5];
    const float* f1b = (const float*)d_in[6];
    const float* f2w = (const float*)d_in[7];
    const float* f2b = (const float*)d_in[8];
    float* out = (float*)d_out;

    prep_kernel<<<1, 256>>>(w1, b1, w2, b2, f1w, f1b, f2w, f2b);
    conv1_kernel<<<2048, 256>>>((const float4*)x, out);
    conv2_kernel<<<2048, 160>>>(out);
    fc_kernel<<<128, 256>>>(out);
}

// round 8
// speedup vs baseline: 2.1468x; 1.1468x over previous
#include <cuda_runtime.h>

// ---------------------------------------------------------------------------
// Quantized LeNet, exact fixed-point semantics.
// APREC=8, PPREC=8, IWIDTH=3 -> clamp to [-8.0, +7.0], grid 1/256.
//
// round_half_even(x*w256) == fmaf(x, w256, MAGIC) - MAGIC (MAGIC=1.5*2^23).
// Conv fast path (per-block proof the clamp is a no-op): fma.rn.f32x2 rounds
// TWO pixels per fma instruction; IADD3 merges two 32-bit halves per alu op;
// magic bias removed once via acc init = bias - ntaps*MAGICI (mod 2^32).
// Clamped scalar fallback per block keeps ANY input exact.
// R8: fc v3 — transposed L1-resident weights (no smem staging), 4 rows/block,
// grid 512; prep parallelized to 64 blocks with idempotent atomicMax.
// ---------------------------------------------------------------------------

typedef unsigned long long ull;

#define MAGICF 12582912.0f
#define MAGICI 0x4B400000u
#define MAGICIi 0x4B400000
#define MAGIC2 0x4B4000004B400000ULL
#define CLAMP_LO (MAGICF - 2048.0f)
#define CLAMP_HI (MAGICF + 1792.0f)   // QMAX = +7.0
#define QLO (-2048)
#define QHI 1792
#define SAFE_BOUND 458624             // 1792*256 - 128

#define OFF_LOGP   0
#define OFF_C1IN   20480
#define OFF_C1OUT  1626112
#define OFF_C2IN   13422592
#define OFF_C2OUT  16371712
#define OFF_FC1IN  18993152
#define OFF_FC1OUT 19648512
#define OFF_FC2IN  19750912
#define OFF_FC2OUT 19853312

__device__ ull   g_w1b[256];         // conv1 w*256 broadcast pairs (w,w)
__device__ int   g_b1[16];
__device__ ull   g_w2b[6016];        // conv2 broadcast pairs, [20][10][5][6]
__device__ int   g_b2[32];
__device__ short g_w1t[320 * 64];    // fc1 w transposed [k][o], o padded to 64
__device__ int   g_f1b[64];
__device__ short g_w2t[50 * 16];     // fc2 w transposed [k][o], o padded to 16
__device__ int   g_f2b[16];
__device__ int   g_maxw1 = 0;        // atomicMax targets (idempotent: weights
__device__ int   g_maxw2 = 0;        // are constant across graph replays)

__device__ __forceinline__ int iclamp(int v, int lo, int hi) {
    return v < lo ? lo : (v > hi ? hi : v);
}
__device__ __forceinline__ int rhe8(int S) {
    return (S + 127 + ((S >> 8) & 1)) >> 8;
}
__device__ __forceinline__ unsigned lo32(ull v) { return (unsigned)v; }
__device__ __forceinline__ unsigned hi32(ull v) { return (unsigned)(v >> 32); }
__device__ __forceinline__ ull mkpack(unsigned lo, unsigned hi) {
    ull d;
    asm("mov.b64 %0, {%1, %2};" : "=l"(d) : "r"(lo), "r"(hi));
    return d;
}
__device__ __forceinline__ ull ffma2m(ull x, ull w) {
    ull d;
    ull m = MAGIC2;
    asm("fma.rn.f32x2 %0, %1, %2, %3;" : "=l"(d) : "l"(x), "l"(w), "l"(m));
    return d;
}

template <int NW>
__device__ __forceinline__ void blockAtomicMax(int v, int* dst) {
    __shared__ int sm[NW];
    v = __reduce_max_sync(0xffffffffu, v);
    int w = threadIdx.x >> 5;
    if ((threadIdx.x & 31) == 0) sm[w] = v;
    __syncthreads();
    if (threadIdx.x == 0) {
        int m = sm[0];
#pragma unroll
        for (int i = 1; i < NW; i++) m = max(m, sm[i]);
        atomicMax(dst, m);
    }
}

// ---------------------------------------------------------------------------
// prep: 64 blocks x 256 threads, grid-stride over every table.
__global__ void __launch_bounds__(256) prep_kernel(
        const float* __restrict__ w1, const float* __restrict__ b1,
        const float* __restrict__ w2, const float* __restrict__ b2,
        const float* __restrict__ f1w, const float* __restrict__ f1b,
        const float* __restrict__ f2w, const float* __restrict__ f2b) {
    int gt = blockIdx.x * 256 + threadIdx.x;
    const int gs = 64 * 256;
    int m1 = 0, m2 = 0;

    for (int i = gt; i < 250; i += gs) {
        float q = rintf(w1[i] * 256.0f);
        unsigned u = __float_as_uint(q);
        g_w1b[i] = ((ull)u << 32) | u;
        m1 = max(m1, abs((int)q));
    }
    for (int i = gt; i < 10; i += gs) g_b1[i] = __float2int_rn(b1[i] * 256.0f);
    for (int i = gt; i < 6000; i += gs) {
        int q = i % 6;
        int rest = i / 6;
        int p = rest % 5;
        int cc = rest / 5;            // cout*10 + cin
        int cin = cc % 10;
        int cout = cc / 10;
        float v = 0.0f;
        if (q < 5) {
            v = rintf(w2[((cout * 10 + cin) * 5 + p) * 5 + q] * 256.0f);
            m2 = max(m2, abs((int)v));
        }
        unsigned u = __float_as_uint(v);
        g_w2b[i] = ((ull)u << 32) | u;
    }
    for (int i = gt; i < 20; i += gs) g_b2[i] = __float2int_rn(b2[i] * 256.0f);

    // fc1 weights transposed: w1t[k*64+o] = clamp(round(f1w[o*320+k]*256))
    for (int i = gt; i < 320 * 64; i += gs) {
        int k = i >> 6;
        int o = i & 63;
        short v = 0;
        if (o < 50) v = (short)iclamp(__float2int_rn(f1w[o * 320 + k] * 256.0f),
                                      QLO, QHI);
        g_w1t[i] = v;
    }
    for (int i = gt; i < 50; i += gs)
        g_f1b[i] = iclamp(__float2int_rn(f1b[i] * 256.0f), QLO, QHI);
    for (int i = gt; i < 50 * 16; i += gs) {
        int k = i >> 4;
        int o = i & 15;
        short v = 0;
        if (o < 10) v = (short)iclamp(__float2int_rn(f2w[o * 50 + k] * 256.0f),
                                      QLO, QHI);
        g_w2t[i] = v;
    }
    for (int i = gt; i < 10; i += gs)
        g_f2b[i] = iclamp(__float2int_rn(f2b[i] * 256.0f), QLO, QHI);

    blockAtomicMax<8>(m1, &g_maxw1);
    __syncthreads();
    blockAtomicMax<8>(m2, &g_maxw2);
}

// ---------------------------------------------------------------------------
// conv1 (+ input quant + pool1), one image per 256-thread block.

__device__ __forceinline__ void c1taps6(unsigned* acc, const ull* E, const ull* O,
                                        const ull* w) {
    ull w0 = w[0];
    ull w1 = w[1];
    ull w2 = w[2];
    ull w3 = w[3];
    ull w4 = w[4];
#pragma unroll
    for (int k = 0; k < 6; k++) {
        ull y0 = ffma2m(E[k], w0);
        ull y1 = ffma2m(O[k], w1);
        ull y2 = ffma2m(E[k + 1], w2);
        ull y3 = ffma2m(O[k + 1], w3);
        ull y4 = ffma2m(E[k + 2], w4);
        acc[2 * k] = acc[2 * k] + lo32(y0) + lo32(y1);
        acc[2 * k] = acc[2 * k] + lo32(y2) + lo32(y3);
        acc[2 * k] = acc[2 * k] + lo32(y4);
        acc[2 * k + 1] = acc[2 * k + 1] + hi32(y0) + hi32(y1);
        acc[2 * k + 1] = acc[2 * k + 1] + hi32(y2) + hi32(y3);
        acc[2 * k + 1] = acc[2 * k + 1] + hi32(y4);
    }
}

__device__ __forceinline__ void conv1_epilogue(float* dout, int b, int co, int R,
                                               int h, const int* acc0,
                                               const int* acc1) {
    float* Ox = dout + OFF_C1OUT + ((b * 10 + co) * 24 + 2 * R) * 24 + 12 * h;
#pragma unroll
    for (int j = 0; j < 12; j += 4) {
        float4 v0, v1;
        v0.x = __int2float_rn(acc0[j + 0]) * 0.00390625f;
        v0.y = __int2float_rn(acc0[j + 1]) * 0.00390625f;
        v0.z = __int2float_rn(acc0[j + 2]) * 0.00390625f;
        v0.w = __int2float_rn(acc0[j + 3]) * 0.00390625f;
        v1.x = __int2float_rn(acc1[j + 0]) * 0.00390625f;
        v1.y = __int2float_rn(acc1[j + 1]) * 0.00390625f;
        v1.z = __int2float_rn(acc1[j + 2]) * 0.00390625f;
        v1.w = __int2float_rn(acc1[j + 3]) * 0.00390625f;
        *(float4*)(Ox + j) = v0;
        *(float4*)(Ox + 24 + j) = v1;
    }
    float* P = dout + OFF_C2IN + ((b * 10 + co) * 12 + R) * 12 + 6 * h;
#pragma unroll
    for (int j = 0; j < 6; j += 2) {
        int m0 = max(max(acc0[2 * j], acc0[2 * j + 1]),
                     max(acc1[2 * j], acc1[2 * j + 1]));
        int m1 = max(max(acc0[2 * j + 2], acc0[2 * j + 3]),
                     max(acc1[2 * j + 2], acc1[2 * j + 3]));
        m0 = max(m0, 0);
        m1 = max(m1, 0);
        float2 v;
        v.x = m0 * 0.00390625f;
        v.y = m1 * 0.00390625f;
        *(float2*)(P + j) = v;
    }
}

__global__ void __launch_bounds__(256) conv1_kernel(const float4* __restrict__ xin,
                                                    float* __restrict__ dout) {
    __shared__ __align__(16) float sx[784];
    __shared__ __align__(16) ull sw[250];
    __shared__ int red[8];

    int b = blockIdx.x;
    int t = threadIdx.x;

    int mx = 0;
    if (t < 196) {
        float4 v = xin[b * 196 + t];
        int q0 = __float2int_rn(v.x * 256.0f);
        int q1 = __float2int_rn(v.y * 256.0f);
        int q2 = __float2int_rn(v.z * 256.0f);
        int q3 = __float2int_rn(v.w * 256.0f);
        v.x = q0 * 0.00390625f; v.y = q1 * 0.00390625f;
        v.z = q2 * 0.00390625f; v.w = q3 * 0.00390625f;
        ((float4*)sx)[t] = v;
        ((float4*)(dout + OFF_C1IN + b * 784))[t] = v;
        mx = max(max(abs(q0), abs(q1)), max(abs(q2), abs(q3)));
    }
    if (t < 250) sw[t] = g_w1b[t];

    mx = __reduce_max_sync(0xffffffffu, mx);
    if ((t & 31) == 0) red[t >> 5] = mx;
    __syncthreads();
    int xmax = red[0];
#pragma unroll
    for (int i = 1; i < 8; i++) xmax = max(xmax, red[i]);
    bool safe = (long long)xmax * (long long)g_maxw1 <= SAFE_BOUND;

    if (t >= 240) return;
    int co = t / 24;
    int rem = t % 24;
    int R = rem >> 1;
    int h = t & 1;
    const float* X = sx + R * 56 + 12 * h;

    if (safe) {
        unsigned bias = (unsigned)g_b1[co] - 25u * MAGICI;
        unsigned acc0[12], acc1[12];
#pragma unroll
        for (int j = 0; j < 12; j++) { acc0[j] = bias; acc1[j] = bias; }
#pragma unroll
        for (int rr = 0; rr < 6; rr++) {
            ull E[8];
            const ulonglong2* xp = (const ulonglong2*)(X + rr * 28);
#pragma unroll
            for (int i = 0; i < 4; i++) {
                ulonglong2 v = xp[i];
                E[2 * i] = v.x;
                E[2 * i + 1] = v.y;
            }
            ull O[7];
#pragma unroll
            for (int i = 0; i < 7; i++) O[i] = mkpack(hi32(E[i]), lo32(E[i + 1]));
            if (rr < 5)  c1taps6(acc0, E, O, sw + co * 25 + rr * 5);
            if (rr >= 1) c1taps6(acc1, E, O, sw + co * 25 + (rr - 1) * 5);
        }
        conv1_epilogue(dout, b, co, R, h, (const int*)acc0, (const int*)acc1);
    } else {
        int bq = g_b1[co];
        int acc0[12], acc1[12];
#pragma unroll
        for (int j = 0; j < 12; j++) { acc0[j] = bq; acc1[j] = bq; }
#pragma unroll
        for (int rr = 0; rr < 6; rr++) {
            float xr[16];
#pragma unroll
            for (int i = 0; i < 4; i++) {
                float4 v = ((const float4*)(X + rr * 28))[i];
                xr[4 * i + 0] = v.x; xr[4 * i + 1] = v.y;
                xr[4 * i + 2] = v.z; xr[4 * i + 3] = v.w;
            }
#pragma unroll
            for (int pass = 0; pass < 2; pass++) {
                int p = pass == 0 ? rr : rr - 1;
                if (p < 0 || p > 4) continue;
                int* acc = pass == 0 ? acc0 : acc1;
#pragma unroll
                for (int q = 0; q < 5; q++) {
                    float w = __uint_as_float(lo32(sw[co * 25 + p * 5 + q]));
#pragma unroll
                    for (int j = 0; j < 12; j++) {
                        float y = fmaf(xr[j + q], w, MAGICF);
                        y = fminf(fmaxf(y, CLAMP_LO), CLAMP_HI);
                        acc[j] += __float_as_int(y) - MAGICIi;
                    }
                }
            }
        }
        conv1_epilogue(dout, b, co, R, h, acc0, acc1);
    }
}

// ---------------------------------------------------------------------------
// conv2: block = 160 threads = (2 images x 10 couts x 8 rows).

template <bool CONSUME>
__device__ __forceinline__ void c2step(unsigned acc[8], ull carry[4],
                                       const float* Xrow, const ull* wp) {
    ull E[6];
    const ulonglong2* xp = (const ulonglong2*)Xrow;
#pragma unroll
    for (int i = 0; i < 3; i++) {
        ulonglong2 v = xp[i];
        E[2 * i] = v.x;
        E[2 * i + 1] = v.y;
    }
    ull O[5];
#pragma unroll
    for (int i = 0; i < 5; i++) O[i] = mkpack(hi32(E[i]), lo32(E[i + 1]));
    const ulonglong2* wv = (const ulonglong2*)wp;
    ulonglong2 wa = wv[0];
    ulonglong2 wb = wv[1];
    ulonglong2 wc = wv[2];
#pragma unroll
    for (int k = 0; k < 4; k++) {
        ull y0 = ffma2m(E[k], wa.x);
        ull y1 = ffma2m(O[k], wa.y);
        ull y2 = ffma2m(E[k + 1], wb.x);
        ull y3 = ffma2m(O[k + 1], wb.y);
        ull y4 = ffma2m(E[k + 2], wc.x);
        acc[2 * k] = acc[2 * k] + lo32(y0) + lo32(y1);
        acc[2 * k] = acc[2 * k] + lo32(y2) + lo32(y3);
        acc[2 * k + 1] = acc[2 * k + 1] + hi32(y0) + hi32(y1);
        acc[2 * k + 1] = acc[2 * k + 1] + hi32(y2) + hi32(y3);
        if (CONSUME) {
            acc[2 * k]     = acc[2 * k]     + lo32(y4) + lo32(carry[k]);
            acc[2 * k + 1] = acc[2 * k + 1] + hi32(y4) + hi32(carry[k]);
        } else {
            carry[k] = y4;
        }
    }
}

__global__ void __launch_bounds__(160) conv2_kernel(float* __restrict__ dout) {
    __shared__ __align__(16) float sx[2880];
    __shared__ __align__(16) ull sw[3000];
    __shared__ int red[5];

    int blk = blockIdx.x;     // 0..2047
    int ip = blk >> 1;        // image pair index
    int g = blk & 1;          // cout group (couts 10g..10g+9)
    int t = threadIdx.x;

    const ulonglong2* wsrc = (const ulonglong2*)(g_w2b + g * 3000);
    for (int i = t; i < 1500; i += 160) ((ulonglong2*)sw)[i] = wsrc[i];

    const float4* xs = (const float4*)(dout + OFF_C2IN + ip * 2880);
    int mx = 0;
    for (int i = t; i < 720; i += 160) {
        float4 v = xs[i];
        ((float4*)sx)[i] = v;
        int q0 = __float2int_rn(v.x * 256.0f);
        int q1 = __float2int_rn(v.y * 256.0f);
        int q2 = __float2int_rn(v.z * 256.0f);
        int q3 = __float2int_rn(v.w * 256.0f);
        mx = max(mx, max(max(abs(q0), abs(q1)), max(abs(q2), abs(q3))));
    }
    mx = __reduce_max_sync(0xffffffffu, mx);
    if ((t & 31) == 0) red[t >> 5] = mx;
    __syncthreads();
    int xmax = red[0];
#pragma unroll
    for (int i = 1; i < 5; i++) xmax = max(xmax, red[i]);
    bool safe = (long long)xmax * (long long)g_maxw2 <= SAFE_BOUND;

    int img = t / 80;
    int r = t % 80;
    int co_local = r / 8;
    int row = r % 8;
    int co = g * 10 + co_local;
    const float* X = sx + img * 1440;
    const ull* W = sw + co_local * 300;
    int bi = ip * 2 + img;

    if (safe) {
        unsigned acc[8];
        unsigned bias = (unsigned)g_b2[co] - 250u * MAGICI;
#pragma unroll
        for (int j = 0; j < 8; j++) acc[j] = bias;
        ull carry[4];
#pragma unroll 1
        for (int ci2 = 0; ci2 < 5; ci2++) {
            int cA = 2 * ci2;
            const float* Xa = X + cA * 144 + row * 12;
            const ull* Wa = W + cA * 30;
            c2step<false>(acc, carry, Xa + 0 * 12, Wa + 0);
            c2step<true >(acc, carry, Xa + 1 * 12, Wa + 6);
            c2step<false>(acc, carry, Xa + 2 * 12, Wa + 12);
            c2step<true >(acc, carry, Xa + 3 * 12, Wa + 18);
            c2step<false>(acc, carry, Xa + 4 * 12, Wa + 24);
            const float* Xb = Xa + 144;
            const ull* Wb = Wa + 30;
            c2step<true >(acc, carry, Xb + 0 * 12, Wb + 0);
            c2step<false>(acc, carry, Xb + 1 * 12, Wb + 6);
            c2step<true >(acc, carry, Xb + 2 * 12, Wb + 12);
            c2step<false>(acc, carry, Xb + 3 * 12, Wb + 18);
            c2step<true >(acc, carry, Xb + 4 * 12, Wb + 24);
        }
        float* O = dout + OFF_C2OUT + ((bi * 20 + co) * 8 + row) * 8;
#pragma unroll
        for (int j = 0; j < 8; j += 4) {
            float4 v;
            v.x = __int2float_rn((int)acc[j + 0]) * 0.00390625f;
            v.y = __int2float_rn((int)acc[j + 1]) * 0.00390625f;
            v.z = __int2float_rn((int)acc[j + 2]) * 0.00390625f;
            v.w = __int2float_rn((int)acc[j + 3]) * 0.00390625f;
            *(float4*)(O + j) = v;
        }
    } else {
        int acc[8];
        int bq = g_b2[co];
#pragma unroll
        for (int j = 0; j < 8; j++) acc[j] = bq;
#pragma unroll 1
        for (int ci = 0; ci < 10; ci++) {
#pragma unroll
            for (int p = 0; p < 5; p++) {
                float xr[12];
                const float4* xp = (const float4*)(X + ci * 144 + (row + p) * 12);
#pragma unroll
                for (int i = 0; i < 3; i++) {
                    float4 v = xp[i];
                    xr[4 * i + 0] = v.x; xr[4 * i + 1] = v.y;
                    xr[4 * i + 2] = v.z; xr[4 * i + 3] = v.w;
                }
                const ull* wp = W + (ci * 5 + p) * 6;
#pragma unroll
                for (int q = 0; q < 5; q++) {
                    float w = __uint_as_float(lo32(wp[q]));
#pragma unroll
                    for (int j = 0; j < 8; j++) {
                        float y = fmaf(xr[j + q], w, MAGICF);
                        y = fminf(fmaxf(y, CLAMP_LO), CLAMP_HI);
                        acc[j] += __float_as_int(y) - MAGICIi;
                    }
                }
            }
        }
        float* O = dout + OFF_C2OUT + ((bi * 20 + co) * 8 + row) * 8;
#pragma unroll
        for (int j = 0; j < 8; j += 4) {
            float4 v;
            v.x = __int2float_rn(acc[j + 0]) * 0.00390625f;
            v.y = __int2float_rn(acc[j + 1]) * 0.00390625f;
            v.z = __int2float_rn(acc[j + 2]) * 0.00390625f;
            v.w = __int2float_rn(acc[j + 3]) * 0.00390625f;
            *(float4*)(O + j) = v;
        }
    }
}

// ---------------------------------------------------------------------------
// fc v3: block = 256 threads, 4 batch rows, grid 512. Weights from L1-resident
// transposed globals (coalesced LDG.16); x broadcast from tiny smem.
// pool2 -> fc1_input -> FC1 -> relu -> FC2 -> log_softmax, all fused.
__global__ void __launch_bounds__(256) fc_kernel(float* __restrict__ dout) {
    __shared__ short xqs[4 * 320];
    __shared__ short x2s[4 * 64];
    __shared__ float v2s[4 * 16];

    int t = threadIdx.x;
    int blk = blockIdx.x;               // rows blk*4 .. blk*4+3

    // phase 1: pool2 + relu + quant (writes fc1_input)
#pragma unroll
    for (int ii = 0; ii < 5; ii++) {
        int i = ii * 256 + t;           // 1280 items
        int r = i / 320;
        int k = i % 320;
        int rowI = blk * 4 + r;
        int c = k >> 4;
        int rem = k & 15;
        int rr = rem >> 2;
        int col = rem & 3;
        const float* base = dout + OFF_C2OUT + rowI * 1280 + c * 64 + 2 * rr * 8 + 2 * col;
        float2 a = *(const float2*)base;
        float2 d = *(const float2*)(base + 8);
        float m = fmaxf(fmaxf(a.x, a.y), fmaxf(d.x, d.y));
        m = fmaxf(m, 0.0f);
        dout[OFF_FC1IN + rowI * 320 + k] = m;
        int q = __float2int_rn(m * 256.0f);
        xqs[r * 320 + k] = (short)iclamp(q, QLO, QHI);
    }
    __syncthreads();

    // phase 2: FC1. thread = (o = t%50, r = t/50), 200 active
    if (t < 200) {
        int o = t % 50;
        int r = t / 50;
        int S = g_f1b[o] << 8;
        const short* xx = &xqs[r * 320];
        const short* wp = &g_w1t[o];
#pragma unroll 8
        for (int k = 0; k < 320; k++) S += (int)xx[k] * (int)wp[k * 64];
        S = iclamp(S, -524288, 458752);   // [-8, 7] * 65536
        int q = rhe8(S);
        int rowI = blk * 4 + r;
        float f = q * 0.00390625f;
        dout[OFF_FC1OUT + rowI * 50 + o] = f;
        int qr = q > 0 ? q : 0;
        dout[OFF_FC2IN + rowI * 50 + o] = qr * 0.00390625f;
        x2s[r * 64 + o] = (short)qr;
    }
    __syncthreads();

    // phase 3: FC2 (40 dots of length 50)
    if (t < 40) {
        int r = t / 10;
        int o = t % 10;
        int S = g_f2b[o] << 8;
        const short* xx = &x2s[r * 64];
        const short* wp = &g_w2t[o];
#pragma unroll
        for (int k = 0; k < 50; k++) S += (int)xx[k] * (int)wp[k * 16];
        S = iclamp(S, -524288, 458752);
        int q = rhe8(S);
        float f = q * 0.00390625f;
        int rowI = blk * 4 + r;
        dout[OFF_FC2OUT + rowI * 10 + o] = f;
        v2s[r * 16 + o] = f;
    }
    __syncthreads();

    // phase 4: log_softmax
    if (t < 40) {
        int r = t / 10;
        int o = t % 10;
        const float* v = &v2s[r * 16];
        float m = v[0];
#pragma unroll
        for (int k = 1; k < 10; k++) m = fmaxf(m, v[k]);
        float s = 0.0f;
#pragma unroll
        for (int k = 0; k < 10; k++) s += expf(v[k] - m);
        int rowI = blk * 4 + r;
        dout[OFF_LOGP + rowI * 10 + o] = v[o] - m - logf(s);
    }
}

// ---------------------------------------------------------------------------
extern "C" void kernel_launch(void* const* d_in, const int* in_sizes, int n_in,
                              void* d_out, int out_size) {
    const float* x   = (const float*)d_in[0];
    const float* w1  = (const float*)d_in[1];
    const float* b1  = (const float*)d_in[2];
    const float* w2  = (const float*)d_in[3];
    const float* b2  = (const float*)d_in[4];
    const float* f1w = (const float*)d_in[5];
    const float* f1b = (const float*)d_in[6];
    const float* f2w = (const float*)d_in[7];
    const float* f2b = (const float*)d_in[8];
    float* out = (float*)d_out;

    prep_kernel<<<64, 256>>>(w1, b1, w2, b2, f1w, f1b, f2w, f2b);
    conv1_kernel<<<2048, 256>>>((const float4*)x, out);
    conv2_kernel<<<2048, 160>>>(out);
    fc_kernel<<<512, 256>>>(out);
}